// round 15
// baseline (speedup 1.0000x reference)
#include <cuda_runtime.h>
#include <cuda_fp16.h>
#include <math.h>
#include <stdint.h>

// Problem constants
#define Bq   512
#define NPGc 50
#define EPGc 60
#define Dd   128
#define Vv   100000
#define NSPLITS 4
#define NSCALE 12.0f
#define NN   (Bq*NPGc)   // 25600 nodes
#define EE   (Bq*EPGc)   // 30720 edges
#define ND   (NN*Dd)

// ---------------- scratch (device globals) ----------------------------------
__device__ float g_feat[ND];
__device__ float g_nv[3*NN];       // den1 | den2 | deg
__device__ float g_gi[NN*384];     // gi / Gx
__device__ float g_gh[NN*384];     // gh / Gh
__device__ float g_x[ND];
__device__ float g_h[ND];
__device__ float g_t1[ND];
__device__ float g_t2[ND];
__device__ float g_zz[ND];
__device__ float g_emf[EE];
__device__ float g_tend[1];
__device__ float g_sc[Vv];
__device__ float g_q[Bq*Dd];
__device__ float g_cc[Bq*2*Dd];
__device__ float g_sr[Bq*Dd];
__device__ float g_expsum[Bq];
// fp16 mirrors ---------------------------------------------------------------
__device__ __half g_agg16[3*ND];   // aggx | aggh | aggrh (also num1|num2)
__device__ __half g_feat16[ND];
__device__ __half g_cc16[Bq*2*Dd];
__device__ __half g_sr16[Bq*Dd];
__device__ __half g_emb16[(size_t)Vv*Dd];
__device__ __half g_gwih16[384*256];
__device__ __half g_w116[128*128];
__device__ __half g_w216[128*128];
__device__ __half g_gwhh16[384*128];
__device__ __half g_wcxT16[384*128];  // [Wxr|Wxz|Wxh]^T
__device__ __half g_wchT16[256*128];  // [Whr|Whz]^T
__device__ __half g_whhT16[128*128];
__device__ __half g_wuT16 [128*128];
__device__ __half g_wvT16 [128*128];
__device__ __half g_wsrT16[128*256];
__device__ __half g_wc1T16[384*128];
__device__ __half g_wc2T16[384*128];
__device__ float g_bcx[384];
__device__ float g_bch[256];

// ---------------- fp16 tensor-core GEMM (round-12 proven config) --------------
// C[r,n] (+= if accum) = RS(r) * (sum_k A[r,k]*B[n,k]) * colscale[n] + bias[n]
// rsMode: 0 = rowscale[r]; 1 = (den==0?1:1/den); 2 = rsqrt(max(deg,1)).
// expsum: accumulate sum_n exp(v-12) per row (logits mode).
__device__ __forceinline__ void cph16(uint32_t dst, const __half* src, bool pred){
    int sz = pred ? 16 : 0;
    asm volatile("cp.async.cg.shared.global [%0], [%1], 16, %2;"
                 :: "r"(dst), "l"(src), "r"(sz));
}

__global__ __launch_bounds__(256)
void k_gemm_h(const __half* __restrict__ A, int lda,
              const __half* __restrict__ Bm, int ldb,
              const float* __restrict__ bias,
              const float* __restrict__ colscale,
              const float* __restrict__ rowscale, int rsMode,
              float* __restrict__ C, int ldc,
              float* __restrict__ expsum,
              int Nr, int Mc, int K, int accum)
{
    __shared__ __half sA[2][128*40];   // [row][k], row stride 40 halves
    __shared__ __half sB[2][128*40];
    int brow = blockIdx.x*128;
    int bcol = blockIdx.y*128;
    int tid  = threadIdx.x;
    int warp = tid >> 5, lane = tid & 31;
    int gid  = lane >> 2, tig = lane & 3;
    int wm   = (warp & 3) * 32;
    int wn   = (warp >> 2) * 64;

    float acc[2][8][4];
    #pragma unroll
    for (int mt = 0; mt < 2; mt++)
        #pragma unroll
        for (int nt = 0; nt < 8; nt++)
            #pragma unroll
            for (int f = 0; f < 4; f++) acc[mt][nt][f] = 0.f;

    int nchunk = K >> 5;

    auto stage = [&](int st, int gk0){
        uint32_t sap = (uint32_t)__cvta_generic_to_shared(&sA[st][0]);
        uint32_t sbp = (uint32_t)__cvta_generic_to_shared(&sB[st][0]);
        #pragma unroll
        for (int j = 0; j < 2; j++){
            int c   = tid + j*256;
            int row = c >> 2;
            int kq  = c & 3;
            int gr  = brow + row;
            cph16(sap + (uint32_t)(row*80 + kq*16),
                  A + (size_t)gr*lda + gk0 + kq*8, gr < Nr);
        }
        #pragma unroll
        for (int j = 0; j < 2; j++){
            int c   = tid + j*256;
            int row = c >> 2;
            int kq  = c & 3;
            int gm  = bcol + row;
            cph16(sbp + (uint32_t)(row*80 + kq*16),
                  Bm + (size_t)gm*ldb + gk0 + kq*8, gm < Mc);
        }
    };

    stage(0, 0);
    asm volatile("cp.async.commit_group;");

    for (int kc = 0; kc < nchunk; kc++){
        if (kc + 1 < nchunk){ stage((kc+1)&1, (kc+1)*32); }
        asm volatile("cp.async.commit_group;");
        asm volatile("cp.async.wait_group 1;");
        __syncthreads();

        const __half* sa = sA[kc & 1];
        const __half* sb = sB[kc & 1];
        #pragma unroll
        for (int ks = 0; ks < 32; ks += 16){
            uint32_t a[2][4], b[8][2];
            #pragma unroll
            for (int mt = 0; mt < 2; mt++){
                int rb = wm + mt*16;
                a[mt][0] = *(const uint32_t*)&sa[(rb+gid  )*40 + ks + 2*tig    ];
                a[mt][1] = *(const uint32_t*)&sa[(rb+gid+8)*40 + ks + 2*tig    ];
                a[mt][2] = *(const uint32_t*)&sa[(rb+gid  )*40 + ks + 2*tig + 8];
                a[mt][3] = *(const uint32_t*)&sa[(rb+gid+8)*40 + ks + 2*tig + 8];
            }
            #pragma unroll
            for (int nt = 0; nt < 8; nt++){
                int cb = wn + nt*8;
                b[nt][0] = *(const uint32_t*)&sb[(cb+gid)*40 + ks + 2*tig    ];
                b[nt][1] = *(const uint32_t*)&sb[(cb+gid)*40 + ks + 2*tig + 8];
            }
            #pragma unroll
            for (int mt = 0; mt < 2; mt++)
                #pragma unroll
                for (int nt = 0; nt < 8; nt++)
                    asm volatile(
                        "mma.sync.aligned.m16n8k16.row.col.f32.f16.f16.f32 "
                        "{%0,%1,%2,%3}, {%4,%5,%6,%7}, {%8,%9}, {%0,%1,%2,%3};"
                        : "+f"(acc[mt][nt][0]), "+f"(acc[mt][nt][1]),
                          "+f"(acc[mt][nt][2]), "+f"(acc[mt][nt][3])
                        : "r"(a[mt][0]), "r"(a[mt][1]), "r"(a[mt][2]), "r"(a[mt][3]),
                          "r"(b[nt][0]), "r"(b[nt][1]));
        }
        __syncthreads();
    }

    #pragma unroll
    for (int mt = 0; mt < 2; mt++){
        #pragma unroll
        for (int half = 0; half < 2; half++){
            int r = brow + wm + mt*16 + gid + half*8;
            float rs = 1.f;
            if (rowscale && r < Nr){
                float dv = rowscale[r];
                rs = (rsMode == 1) ? ((dv == 0.f) ? 1.f : 1.f/dv)
                   : (rsMode == 2) ? rsqrtf(fmaxf(dv, 1.f)) : dv;
            }
            float es = 0.f;
            if (r < Nr){
                #pragma unroll
                for (int nt = 0; nt < 8; nt++){
                    int c0 = bcol + wn + nt*8 + tig*2;
                    #pragma unroll
                    for (int jj = 0; jj < 2; jj++){
                        int cm = c0 + jj;
                        if (cm >= Mc) continue;
                        float v = acc[mt][nt][half*2 + jj] * rs;
                        if (colscale) v *= colscale[cm];
                        if (bias) v += bias[cm];
                        if (accum) v += C[(size_t)r*ldc + cm];
                        C[(size_t)r*ldc + cm] = v;
                        if (expsum) es += expf(v - 12.f);
                    }
                }
            }
            if (expsum){
                es += __shfl_xor_sync(0xffffffffu, es, 1);
                es += __shfl_xor_sync(0xffffffffu, es, 2);
                if (tig == 0 && r < Nr) atomicAdd(&expsum[r], es);
            }
        }
    }
}

// ---------------- group-local edge kernels (atomic-free) ----------------------
#define EDGEB_SMEM ((2*NPGc*Dd + 2*64)*4)
__global__ void k_edgeB_grp(const int* __restrict__ src, const int* __restrict__ dst,
                            const float* __restrict__ w, const float* __restrict__ feat,
                            __half* __restrict__ num1h, __half* __restrict__ num2h,
                            float* __restrict__ den1, float* __restrict__ den2){
    extern __shared__ float sm[];
    float* n1s = sm;
    float* n2s = sm + NPGc*Dd;
    float* d1s = sm + 2*NPGc*Dd;
    float* d2s = d1s + 64;
    int b = blockIdx.x, d = threadIdx.x;
    for (int i = d; i < NPGc*Dd; i += 128){ n1s[i] = 0.f; n2s[i] = 0.f; }
    if (d < NPGc){ d1s[d] = 0.f; d2s[d] = 0.f; }
    __syncthreads();
    int nb = b*NPGc, eb = b*EPGc;
    for (int e = 0; e < EPGc; e++){
        int ge = eb + e;
        int s = src[ge] - nb, t = dst[ge] - nb;
        float ww = w[ge];
        n1s[t*Dd + d] += feat[(size_t)(nb+s)*Dd + d]*ww;
        n2s[s*Dd + d] += feat[(size_t)(nb+t)*Dd + d]*ww;
        if (d == 0) d1s[t] += ww;
        if (d == 32) d2s[s] += ww;
    }
    __syncthreads();
    for (int i = 0; i < NPGc; i++){
        num1h[(size_t)(nb+i)*Dd + d] = __float2half_rn(n1s[i*Dd + d]);
        num2h[(size_t)(nb+i)*Dd + d] = __float2half_rn(n2s[i*Dd + d]);
    }
    if (d < NPGc){ den1[nb+d] = d1s[d]; den2[nb+d] = d2s[d]; }
}

#define AGG2_SMEM ((2*NPGc*Dd + 64 + 64)*4)
__global__ void k_agg2_grp(const int* __restrict__ src, const int* __restrict__ dst,
                           const float* __restrict__ edge_t, const float* __restrict__ node_t,
                           const float* __restrict__ tend, int kstep,
                           const float* __restrict__ x, const float* __restrict__ h,
                           __half* __restrict__ aggx, __half* __restrict__ aggh,
                           float* __restrict__ emf, float* __restrict__ deg){
    extern __shared__ float sm[];
    float* ax = sm;
    float* ah = sm + NPGc*Dd;
    float* dg = sm + 2*NPGc*Dd;
    float* me = dg + 64;
    int b = blockIdx.x, d = threadIdx.x;
    for (int i = d; i < NPGc*Dd; i += 128){ ax[i] = 0.f; ah[i] = 0.f; }
    if (d < NPGc) dg[d] = 0.f;
    __syncthreads();
    int nb = b*NPGc, eb = b*EPGc;
    if (d < EPGc){
        int ge = eb + d;
        float dt = tend[0] / (float)NSPLITS;
        float t = (float)kstep * dt;
        int s = src[ge] - nb, tt = dst[ge] - nb;
        float m = (edge_t[ge] <= t && node_t[nb+s] >= t && node_t[nb+tt] >= t && s != tt)
                  ? 1.f : 0.f;
        me[d] = m; emf[ge] = m;
        if (m > 0.f){ atomicAdd(&dg[s], 1.f); atomicAdd(&dg[tt], 1.f); }
    }
    __syncthreads();
    for (int e = 0; e < EPGc; e++){
        if (me[e] == 0.f) continue;
        int ge = eb + e;
        int s = src[ge] - nb, t = dst[ge] - nb;
        float ds  = rsqrtf(fmaxf(dg[s], 1.f));
        float dt_ = rsqrtf(fmaxf(dg[t], 1.f));
        float xs = x[(size_t)(nb+s)*Dd + d], xt = x[(size_t)(nb+t)*Dd + d];
        float hs = h[(size_t)(nb+s)*Dd + d], ht = h[(size_t)(nb+t)*Dd + d];
        ax[t*Dd + d] += xs*ds;  ax[s*Dd + d] += xt*dt_;
        ah[t*Dd + d] += hs*ds;  ah[s*Dd + d] += ht*dt_;
    }
    __syncthreads();
    for (int i = 0; i < NPGc; i++){
        aggx[(size_t)(nb+i)*Dd + d] = __float2half_rn(ax[i*Dd + d]);
        aggh[(size_t)(nb+i)*Dd + d] = __float2half_rn(ah[i*Dd + d]);
    }
    if (d < NPGc) deg[nb+d] = dg[d];
}

// fused rz + single aggregate: compute rr/zz from Gx,Gh in-SMEM; rh never hits
// global. Writes zz (for k_upd) and agg16 (rh aggregate).
#define AGG1RZ_SMEM ((2*NPGc*Dd + 64 + 64)*4)
__global__ void k_agg1rz_grp(const int* __restrict__ src, const int* __restrict__ dst,
                             const float* __restrict__ emf, const float* __restrict__ deg,
                             const float* __restrict__ Gx, const float* __restrict__ Gh,
                             const float* __restrict__ h,
                             float* __restrict__ zz, __half* __restrict__ agg){
    extern __shared__ float sm[];
    float* rh = sm;                 // [50*128]
    float* as = sm + NPGc*Dd;       // [50*128]
    float* dg = sm + 2*NPGc*Dd;     // [64]
    float* me = dg + 64;            // [64]
    int b = blockIdx.x, d = threadIdx.x;
    int nb = b*NPGc, eb = b*EPGc;
    if (d < NPGc) dg[d] = deg[nb+d];
    if (d < EPGc) me[d] = emf[eb+d];
    // compute rh into smem + zz to global (coalesced row-wise)
    for (int i = 0; i < NPGc; i++){
        size_t row = (size_t)(nb + i);
        float gx_r = Gx[row*384 + d];
        float gh_r = Gh[row*256 + d];
        float gx_z = Gx[row*384 + 128 + d];
        float gh_z = Gh[row*256 + 128 + d];
        float rr = 1.f/(1.f + expf(-(gx_r + gh_r)));
        zz[row*Dd + d] = 1.f/(1.f + expf(-(gx_z + gh_z)));
        rh[i*Dd + d] = rr * h[row*Dd + d];
        as[i*Dd + d] = 0.f;
    }
    __syncthreads();
    for (int e = 0; e < EPGc; e++){
        if (me[e] == 0.f) continue;
        int ge = eb + e;
        int s = src[ge] - nb, t = dst[ge] - nb;
        float ds  = rsqrtf(fmaxf(dg[s], 1.f));
        float dt_ = rsqrtf(fmaxf(dg[t], 1.f));
        as[t*Dd + d] += rh[s*Dd + d]*ds;
        as[s*Dd + d] += rh[t*Dd + d]*dt_;
    }
    __syncthreads();
    for (int i = 0; i < NPGc; i++)
        agg[(size_t)(nb+i)*Dd + d] = __float2half_rn(as[i*Dd + d]);
}

// ---------------- conversions -------------------------------------------------
__global__ void k_cvt(const float* __restrict__ in, __half* __restrict__ out, int n4){
    int i = blockIdx.x*256 + threadIdx.x;
    if (i >= n4) return;
    float4 v = ((const float4*)in)[i];
    ((__half2*)out)[2*i]   = __floats2half2_rn(v.x, v.y);
    ((__half2*)out)[2*i+1] = __floats2half2_rn(v.z, v.w);
}

__global__ void k_cvt2(const float* a, __half* ah, int na4,
                       const float* b, __half* bh, int nb4){
    int i = blockIdx.x*256 + threadIdx.x;
    const float* in; __half* out; int j;
    if (i < na4){ in = a; out = ah; j = i; }
    else if (i - na4 < nb4){ in = b; out = bh; j = i - na4; }
    else return;
    float4 v = ((const float4*)in)[j];
    ((__half2*)out)[2*j]   = __floats2half2_rn(v.x, v.y);
    ((__half2*)out)[2*j+1] = __floats2half2_rn(v.z, v.w);
}

__global__ void k_cvtw(const float* gwih, __half* gwih16,
                       const float* W1, __half* w116,
                       const float* W2, __half* w216,
                       const float* gwhh, __half* gwhh16){
    int i = blockIdx.x*256 + threadIdx.x;
    const float* in; __half* out; int j;
    if (i < 24576){ in = gwih; out = gwih16; j = i; }
    else if (i < 28672){ in = W1; out = w116; j = i - 24576; }
    else if (i < 32768){ in = W2; out = w216; j = i - 28672; }
    else if (i < 45056){ in = gwhh; out = gwhh16; j = i - 32768; }
    else return;
    float4 v = ((const float4*)in)[j];
    ((__half2*)out)[2*j]   = __floats2half2_rn(v.x, v.y);
    ((__half2*)out)[2*j+1] = __floats2half2_rn(v.z, v.w);
}

// ---------------- helpers -----------------------------------------------------
__global__ void k_zero2(float* p1, int n1, float* p2, int n2){
    int i = blockIdx.x*256 + threadIdx.x;
    if (i < n1) p1[i] = 0.f;
    else if (i - n1 < n2) p2[i - n1] = 0.f;
}

__global__ void k_gather_norm(const float* __restrict__ emb, const int* __restrict__ iid,
                              float* __restrict__ out, __half* __restrict__ out16){
    int n = blockIdx.x, d = threadIdx.x;
    float v = emb[(size_t)iid[n]*Dd + d];
    float s = v*v;
    #pragma unroll
    for (int o = 16; o; o >>= 1) s += __shfl_xor_sync(0xffffffffu, s, o);
    __shared__ float sh[4];
    if ((d & 31) == 0) sh[d>>5] = s;
    __syncthreads();
    float tot = sh[0]+sh[1]+sh[2]+sh[3];
    float nf = v / fmaxf(sqrtf(tot), 1e-12f);
    out[(size_t)n*Dd + d] = nf;
    out16[(size_t)n*Dd + d] = __float2half_rn(nf);
}

__global__ void k_row_norm_h(const float* __restrict__ in, float* __restrict__ out,
                             __half* __restrict__ out16){
    int n = blockIdx.x, d = threadIdx.x;
    float v = in[(size_t)n*Dd + d];
    float s = v*v;
    #pragma unroll
    for (int o = 16; o; o >>= 1) s += __shfl_xor_sync(0xffffffffu, s, o);
    __shared__ float sh[4];
    if ((d & 31) == 0) sh[d>>5] = s;
    __syncthreads();
    float tot = sh[0]+sh[1]+sh[2]+sh[3];
    float nf = v / fmaxf(sqrtf(tot), 1e-12f);
    out[(size_t)n*Dd + d] = nf;
    if (out16) out16[(size_t)n*Dd + d] = __float2half_rn(nf);
}

__global__ void k_emb_scale(const float* __restrict__ emb, float* __restrict__ sc){
    int v = blockIdx.x, d = threadIdx.x;
    float x = emb[(size_t)v*Dd + d];
    float s = x*x;
    #pragma unroll
    for (int o = 16; o; o >>= 1) s += __shfl_xor_sync(0xffffffffu, s, o);
    __shared__ float sh[4];
    if ((d & 31) == 0) sh[d>>5] = s;
    __syncthreads();
    if (d == 0){
        float tot = sh[0]+sh[1]+sh[2]+sh[3];
        sc[v] = NSCALE / fmaxf(sqrtf(tot), 1e-12f);
    }
}

__global__ void k_pack(const float* Wxr, const float* Wxz, const float* Wxh,
                       const float* Whr, const float* Whz, const float* Whh,
                       const float* Wu, const float* Wv, const float* W_sr,
                       const float* bxr, const float* bxz, const float* bxh,
                       const float* bhr, const float* bhz,
                       __half* WcxT, __half* WchT, __half* WhhT,
                       __half* WuT, __half* WvT, __half* WsrT,
                       float* bcx, float* bch){
    int i = blockIdx.x*256 + threadIdx.x;
    if (i < 49152){
        int j = i >> 7, k = i & 127;
        const float* W = (j < 128) ? Wxr : ((j < 256) ? Wxz : Wxh);
        WcxT[i] = __float2half_rn(W[k*128 + (j & 127)]);
    } else if (i < 81920){
        int t = i - 49152;
        int j = t >> 7, k = t & 127;
        const float* W = (j < 128) ? Whr : Whz;
        WchT[t] = __float2half_rn(W[k*128 + (j & 127)]);
    } else if (i < 98304){
        int t = i - 81920;
        int j = t >> 7, k = t & 127;
        WhhT[t] = __float2half_rn(Whh[k*128 + j]);
    } else if (i < 114688){
        int t = i - 98304;
        int j = t >> 7, k = t & 127;
        WuT[t] = __float2half_rn(Wu[k*128 + j]);
    } else if (i < 131072){
        int t = i - 114688;
        int j = t >> 7, k = t & 127;
        WvT[t] = __float2half_rn(Wv[k*128 + j]);
    } else if (i < 163840){
        int t = i - 131072;
        int j = t >> 8, k = t & 255;
        WsrT[t] = __float2half_rn(W_sr[k*128 + j]);
    } else if (i < 164224){
        int j = i - 163840;
        bcx[j] = (j < 128) ? bxr[j] : ((j < 256) ? bxz[j-128] : bxh[j-256]);
    } else if (i < 164480){
        int j = i - 164224;
        bch[j] = (j < 128) ? bhr[j] : bhz[j-128];
    }
}

// ---------------- fused GRU + l2norm + copy to x,h ----------------------------
__global__ void k_gru_norm(const float* __restrict__ gi, const float* __restrict__ gh,
                           float* __restrict__ feat, float* __restrict__ x,
                           float* __restrict__ h){
    int n = blockIdx.x, d = threadIdx.x;
    size_t b3 = (size_t)n*384 + d;
    float ir = gi[b3], iz = gi[b3+128], ig = gi[b3+256];
    float hr = gh[b3], hz = gh[b3+128], hg = gh[b3+256];
    float r = 1.f/(1.f + expf(-(ir + hr)));
    float z = 1.f/(1.f + expf(-(iz + hz)));
    float g = tanhf(ig + r*hg);
    size_t i = (size_t)n*Dd + d;
    float f = (1.f - z)*g + z*feat[i];
    float s = f*f;
    #pragma unroll
    for (int o = 16; o; o >>= 1) s += __shfl_xor_sync(0xffffffffu, s, o);
    __shared__ float sh[4];
    if ((d & 31) == 0) sh[d>>5] = s;
    __syncthreads();
    float tot = sh[0]+sh[1]+sh[2]+sh[3];
    float nf = f / fmaxf(sqrtf(tot), 1e-12f);
    feat[i] = nf; x[i] = nf; h[i] = nf;
}

__global__ void k_tmax(const float* __restrict__ et, float* tend){
    int i = blockIdx.x*256 + threadIdx.x;
    float v = (i < EE) ? et[i] : 0.f;
    #pragma unroll
    for (int o = 16; o; o >>= 1) v = fmaxf(v, __shfl_xor_sync(0xffffffffu, v, o));
    if ((threadIdx.x & 31) == 0) atomicMax((int*)tend, __float_as_int(v));
}

__global__ void k_upd(const float* __restrict__ Gx, const float* __restrict__ t2,
                      const float* __restrict__ zz, const float* __restrict__ node_t,
                      const float* __restrict__ tend, int kstep, float* __restrict__ h){
    int i = blockIdx.x*256 + threadIdx.x;
    if (i >= ND) return;
    int n = i >> 7, d = i & 127;
    float uu = tanhf(Gx[(size_t)n*384 + 256 + d] + t2[i]);
    float dt = tend[0] / (float)NSPLITS;
    float t = (float)kstep * dt;
    float hv = h[i];
    float dh = (node_t[n] >= t) ? (1.f - zz[i])*(uu - hv) : 0.f;
    h[i] = hv + dt*dh;
}

// ---------------- attention readout (writes f32 + fp16 cc) --------------------
__global__ void k_attn(const float* __restrict__ feat, const float* __restrict__ q,
                       const float* __restrict__ fwu, const float* __restrict__ We,
                       float* __restrict__ cc, __half* __restrict__ cc16){
    int b = blockIdx.x, d = threadIdx.x;
    __shared__ float e_sh[NPGc];
    __shared__ float red[4];
    const float* fb  = feat + (size_t)b*NPGc*Dd;
    const float* fwb = fwu  + (size_t)b*NPGc*Dd;
    float qd = q[(size_t)b*Dd + d];
    float wed = We[d];
    for (int i = 0; i < NPGc; i++){
        float s = (1.f/(1.f + expf(-(fwb[(size_t)i*Dd + d] + qd)))) * wed;
        #pragma unroll
        for (int o = 16; o; o >>= 1) s += __shfl_xor_sync(0xffffffffu, s, o);
        if ((d & 31) == 0) red[d>>5] = s;
        __syncthreads();
        if (d == 0) e_sh[i] = red[0]+red[1]+red[2]+red[3];
        __syncthreads();
    }
    float mx = -1e30f;
    for (int i = 0; i < NPGc; i++) mx = fmaxf(mx, e_sh[i]);
    float sm = 0.f;
    for (int i = 0; i < NPGc; i++) sm += expf(e_sh[i] - mx);
    float srg = 0.f;
    for (int i = 0; i < NPGc; i++) srg += fb[(size_t)i*Dd + d]*(expf(e_sh[i] - mx)/sm);
    float last = fb[(size_t)(NPGc-1)*Dd + d];
    cc[(size_t)b*2*Dd + d]      = last;
    cc[(size_t)b*2*Dd + Dd + d] = srg;
    cc16[(size_t)b*2*Dd + d]      = __float2half_rn(last);
    cc16[(size_t)b*2*Dd + Dd + d] = __float2half_rn(srg);
}

__global__ void k_sub(float* __restrict__ out, const float* __restrict__ expsum){
    int v = blockIdx.x*256 + threadIdx.x;
    int b = blockIdx.y;
    if (v < Vv) out[(size_t)b*Vv + v] -= 12.f + logf(expsum[b]);
}

// ---------------- host orchestration ------------------------------------------
static inline void gemm16(const __half* A, int lda, const __half* B, int ldb,
                          const float* bias, const float* cs,
                          const float* rs, int rsMode,
                          float* C, int ldc, float* expsum,
                          int Nr, int Mc, int K, int accum = 0){
    dim3 grid((Nr + 127)/128, (Mc + 127)/128);
    k_gemm_h<<<grid, 256>>>(A, lda, B, ldb, bias, cs, rs, rsMode,
                            C, ldc, expsum, Nr, Mc, K, accum);
}

extern "C" void kernel_launch(void* const* d_in, const int* in_sizes, int n_in,
                              void* d_out, int out_size)
{
    const int*   iid    = (const int*)  d_in[0];
    const int*   src    = (const int*)  d_in[1];
    const int*   dst    = (const int*)  d_in[2];
    const float* edge_w = (const float*)d_in[3];
    const float* edge_t = (const float*)d_in[4];
    const float* node_t = (const float*)d_in[5];
    const float* emb    = (const float*)d_in[6];
    const float* W1     = (const float*)d_in[7];
    const float* W2     = (const float*)d_in[8];
    const float* gw_ih  = (const float*)d_in[9];
    const float* gw_hh  = (const float*)d_in[10];
    const float* gb_ih  = (const float*)d_in[11];
    const float* gb_hh  = (const float*)d_in[12];
    const float* Wxr = (const float*)d_in[13]; const float* bxr = (const float*)d_in[14];
    const float* Wxz = (const float*)d_in[15]; const float* bxz = (const float*)d_in[16];
    const float* Wxh = (const float*)d_in[17]; const float* bxh = (const float*)d_in[18];
    const float* Whr = (const float*)d_in[19]; const float* bhr = (const float*)d_in[20];
    const float* Whz = (const float*)d_in[21]; const float* bhz = (const float*)d_in[22];
    const float* Whh = (const float*)d_in[23]; const float* bhh = (const float*)d_in[24];
    const float* Wu  = (const float*)d_in[25];
    const float* Wv  = (const float*)d_in[26];
    const float* bv  = (const float*)d_in[27];
    const float* We  = (const float*)d_in[28];
    const float* W_sr= (const float*)d_in[29];
    float* out = (float*)d_out;

    static int s_attr_done = 0;
    if (!s_attr_done){
        cudaFuncSetAttribute(k_edgeB_grp,  cudaFuncAttributeMaxDynamicSharedMemorySize, EDGEB_SMEM);
        cudaFuncSetAttribute(k_agg2_grp,   cudaFuncAttributeMaxDynamicSharedMemorySize, AGG2_SMEM);
        cudaFuncSetAttribute(k_agg1rz_grp, cudaFuncAttributeMaxDynamicSharedMemorySize, AGG1RZ_SMEM);
        s_attr_done = 1;
    }

    float *p_feat,*p_nv,*p_gi,*p_gh,*p_x,*p_h,*p_t1,*p_t2,*p_zz;
    float *p_emf,*p_tend,*p_sc,*p_q,*p_cc,*p_sr,*p_bcx,*p_bch,*p_expsum;
    __half *p_agg16,*p_feat16,*p_cc16,*p_sr16,*p_emb16,*p_gwih16,*p_w116,*p_w216;
    __half *p_gwhh16,*p_wcxT16,*p_wchT16,*p_whhT16,*p_wuT16,*p_wvT16,*p_wsrT16;
    __half *p_wc1T16,*p_wc2T16;
    cudaGetSymbolAddress((void**)&p_feat, g_feat);
    cudaGetSymbolAddress((void**)&p_nv,   g_nv);
    cudaGetSymbolAddress((void**)&p_gi,   g_gi);
    cudaGetSymbolAddress((void**)&p_gh,   g_gh);
    cudaGetSymbolAddress((void**)&p_x,    g_x);
    cudaGetSymbolAddress((void**)&p_h,    g_h);
    cudaGetSymbolAddress((void**)&p_t1,   g_t1);
    cudaGetSymbolAddress((void**)&p_t2,   g_t2);
    cudaGetSymbolAddress((void**)&p_zz,   g_zz);
    cudaGetSymbolAddress((void**)&p_emf,  g_emf);
    cudaGetSymbolAddress((void**)&p_tend, g_tend);
    cudaGetSymbolAddress((void**)&p_sc,   g_sc);
    cudaGetSymbolAddress((void**)&p_q,    g_q);
    cudaGetSymbolAddress((void**)&p_cc,   g_cc);
    cudaGetSymbolAddress((void**)&p_sr,   g_sr);
    cudaGetSymbolAddress((void**)&p_bcx,  g_bcx);
    cudaGetSymbolAddress((void**)&p_bch,  g_bch);
    cudaGetSymbolAddress((void**)&p_expsum, g_expsum);
    cudaGetSymbolAddress((void**)&p_agg16, g_agg16);
    cudaGetSymbolAddress((void**)&p_feat16,g_feat16);
    cudaGetSymbolAddress((void**)&p_cc16, g_cc16);
    cudaGetSymbolAddress((void**)&p_sr16, g_sr16);
    cudaGetSymbolAddress((void**)&p_emb16,g_emb16);
    cudaGetSymbolAddress((void**)&p_gwih16,g_gwih16);
    cudaGetSymbolAddress((void**)&p_w116, g_w116);
    cudaGetSymbolAddress((void**)&p_w216, g_w216);
    cudaGetSymbolAddress((void**)&p_gwhh16,g_gwhh16);
    cudaGetSymbolAddress((void**)&p_wcxT16,g_wcxT16);
    cudaGetSymbolAddress((void**)&p_wchT16,g_wchT16);
    cudaGetSymbolAddress((void**)&p_whhT16,g_whhT16);
    cudaGetSymbolAddress((void**)&p_wuT16, g_wuT16);
    cudaGetSymbolAddress((void**)&p_wvT16, g_wvT16);
    cudaGetSymbolAddress((void**)&p_wsrT16,g_wsrT16);
    cudaGetSymbolAddress((void**)&p_wc1T16,g_wc1T16);
    cudaGetSymbolAddress((void**)&p_wc2T16,g_wc2T16);

    __half* p_aggx16 = p_agg16;
    __half* p_aggh16 = p_agg16 + ND;
    __half* p_aggrh16= p_agg16 + 2*ND;
    float* p_den1  = p_nv;
    float* p_den2  = p_nv + NN;
    float* p_deg   = p_nv + 2*NN;

    // ---- Stage A + weight prep ----
    k_gather_norm<<<NN, 128>>>(emb, iid, p_feat, p_feat16);
    k_emb_scale<<<Vv, 128>>>(emb, p_sc);
    k_cvt<<<((Vv*Dd/4) + 255)/256, 256>>>(emb, p_emb16, Vv*Dd/4);
    k_cvtw<<<(45056 + 255)/256, 256>>>(gw_ih, p_gwih16, W1, p_w116, W2, p_w216,
                                       gw_hh, p_gwhh16);
    k_pack<<<(164480+255)/256, 256>>>(Wxr, Wxz, Wxh, Whr, Whz, Whh, Wu, Wv, W_sr,
                                      bxr, bxz, bxh, bhr, bhz,
                                      p_wcxT16, p_wchT16, p_whhT16, p_wuT16, p_wvT16,
                                      p_wsrT16, p_bcx, p_bch);
    gemm16(p_gwih16,       256, p_w116, 128, nullptr, nullptr, nullptr, 0,
           p_t1, 128, nullptr, 384, 128, 128);
    gemm16(p_gwih16 + 128, 256, p_w216, 128, nullptr, nullptr, nullptr, 0,
           p_t2, 128, nullptr, 384, 128, 128);
    k_cvt2<<<(2*12288 + 255)/256, 256>>>(p_t1, p_wc1T16, 12288, p_t2, p_wc2T16, 12288);

    // ---- Stage B ----
    k_zero2<<<(Bq + 1 + 255)/256, 256>>>(p_expsum, Bq, p_tend, 1);
    k_edgeB_grp<<<Bq, 128, EDGEB_SMEM>>>(src, dst, edge_w, p_feat,
                                         p_aggx16, p_aggh16, p_den1, p_den2);
    k_tmax<<<(EE+255)/256, 256>>>(edge_t, p_tend);

    // ---- Stage C ----
    gemm16(p_aggx16, Dd, p_wc1T16, 128, gb_ih,  nullptr, p_den1, 1,
           p_gi, 384, nullptr, NN, 384, Dd, 0);
    gemm16(p_aggh16, Dd, p_wc2T16, 128, nullptr, nullptr, p_den2, 1,
           p_gi, 384, nullptr, NN, 384, Dd, 1);
    gemm16(p_feat16, Dd, p_gwhh16, 128, gb_hh, nullptr, nullptr, 0,
           p_gh, 384, nullptr, NN, 384, Dd, 0);

    // ---- Stage D ----
    k_gru_norm<<<NN, 128>>>(p_gi, p_gh, p_feat, p_x, p_h);

    // ---- Stage E: ODE (6 launches/step; R12 GEMM config + rz fused into agg1) ----
    for (int k = 0; k < NSPLITS; k++){
        k_agg2_grp<<<Bq, 128, AGG2_SMEM>>>(src, dst, edge_t, node_t, p_tend, k,
                                           p_x, p_h, p_aggx16, p_aggh16, p_emf, p_deg);
        gemm16(p_aggx16, Dd, p_wcxT16, 128, p_bcx, nullptr, p_deg, 2,
               p_gi, 384, nullptr, NN, 384, Dd, 0);
        gemm16(p_aggh16, Dd, p_wchT16, 128, p_bch, nullptr, p_deg, 2,
               p_gh, 256, nullptr, NN, 256, Dd, 0);
        k_agg1rz_grp<<<Bq, 128, AGG1RZ_SMEM>>>(src, dst, p_emf, p_deg,
                                               p_gi, p_gh, p_h, p_zz, p_aggrh16);
        gemm16(p_aggrh16, Dd, p_whhT16, 128, bhh, nullptr, p_deg, 2,
               p_t2, Dd, nullptr, NN, Dd, Dd, 0);
        k_upd<<<(ND+255)/256, 256>>>(p_gi, p_t2, p_zz, node_t, p_tend, k, p_h);
    }
    k_row_norm_h<<<NN, 128>>>(p_h, p_feat, p_feat16);

    // ---- Stage F ----
    gemm16(p_feat16, Dd, p_wuT16, 128, nullptr, nullptr, nullptr, 0,
           p_t1, Dd, nullptr, NN, Dd, Dd, 0);
    gemm16(p_feat16 + (size_t)(NPGc-1)*Dd, NPGc*Dd, p_wvT16, 128, bv, nullptr, nullptr, 0,
           p_q, Dd, nullptr, Bq, Dd, Dd, 0);
    k_attn<<<Bq, 128>>>(p_feat, p_q, p_t1, We, p_cc, p_cc16);
    gemm16(p_cc16, 2*Dd, p_wsrT16, 256, nullptr, nullptr, nullptr, 0,
           p_sr, Dd, nullptr, Bq, Dd, 2*Dd, 0);
    k_row_norm_h<<<Bq, 128>>>(p_sr, p_sr, p_sr16);

    // ---- Stage G ----
    gemm16(p_sr16, Dd, p_emb16, 128, nullptr, p_sc, nullptr, 0,
           out, Vv, p_expsum, Bq, Vv, Dd, 0);
    k_sub<<<dim3((Vv+255)/256, Bq), 256>>>(out, p_expsum);
}

// round 16
// speedup vs baseline: 1.1573x; 1.1573x over previous
#include <cuda_runtime.h>
#include <cuda_fp16.h>
#include <math.h>
#include <stdint.h>

// Problem constants
#define Bq   512
#define NPGc 50
#define EPGc 60
#define Dd   128
#define Vv   100000
#define NSPLITS 4
#define NSCALE 12.0f
#define NN   (Bq*NPGc)   // 25600 nodes
#define EE   (Bq*EPGc)   // 30720 edges
#define ND   (NN*Dd)

// ---------------- scratch (device globals) ----------------------------------
__device__ float g_feat[ND];
__device__ float g_nv[3*NN];       // den1 | den2 | deg
__device__ float g_gi[NN*384];     // gi / Gx
__device__ float g_gh[NN*384];     // gh / Gh
__device__ float g_x[ND];
__device__ float g_h[ND];
__device__ float g_t1[ND];
__device__ float g_t2[ND];
__device__ float g_rh[ND];
__device__ float g_zz[ND];
__device__ float g_emf[EE];
__device__ float g_tend[1];
__device__ float g_sc[Vv];
__device__ float g_q[Bq*Dd];
__device__ float g_cc[Bq*2*Dd];
__device__ float g_sr[Bq*Dd];
__device__ float g_expsum[Bq];
// fp16 mirrors ---------------------------------------------------------------
__device__ __half g_agg16[3*ND];   // aggx | aggh | aggrh (also num1|num2)
__device__ __half g_feat16[ND];
__device__ __half g_cc16[Bq*2*Dd];
__device__ __half g_sr16[Bq*Dd];
__device__ __half g_emb16[(size_t)Vv*Dd];
__device__ __half g_gwih16[384*256];
__device__ __half g_w116[128*128];
__device__ __half g_w216[128*128];
__device__ __half g_gwhh16[384*128];
__device__ __half g_wcxT16[384*128];  // [Wxr|Wxz|Wxh]^T
__device__ __half g_wchT16[256*128];  // [Whr|Whz]^T
__device__ __half g_whhT16[128*128];
__device__ __half g_wuT16 [128*128];
__device__ __half g_wvT16 [128*128];
__device__ __half g_wsrT16[128*256];
__device__ __half g_wc1T16[384*128];
__device__ __half g_wc2T16[384*128];
__device__ float g_bcx[384];
__device__ float g_bch[256];

// ---------------- fp16 tensor-core GEMM (round-12 proven config) --------------
// C[r,n] (+= if accum) = RS(r) * (sum_k A[r,k]*B[n,k]) * colscale[n] + bias[n]
// rsMode: 0 = rowscale[r]; 1 = (den==0?1:1/den); 2 = rsqrt(max(deg,1)).
// expsum: accumulate sum_n exp(v-12) per row (logits mode).
__device__ __forceinline__ void cph16(uint32_t dst, const __half* src, bool pred){
    int sz = pred ? 16 : 0;
    asm volatile("cp.async.cg.shared.global [%0], [%1], 16, %2;"
                 :: "r"(dst), "l"(src), "r"(sz));
}

__global__ __launch_bounds__(256)
void k_gemm_h(const __half* __restrict__ A, int lda,
              const __half* __restrict__ Bm, int ldb,
              const float* __restrict__ bias,
              const float* __restrict__ colscale,
              const float* __restrict__ rowscale, int rsMode,
              float* __restrict__ C, int ldc,
              float* __restrict__ expsum,
              int Nr, int Mc, int K, int accum)
{
    __shared__ __half sA[2][128*40];   // [row][k], row stride 40 halves
    __shared__ __half sB[2][128*40];
    int brow = blockIdx.x*128;
    int bcol = blockIdx.y*128;
    int tid  = threadIdx.x;
    int warp = tid >> 5, lane = tid & 31;
    int gid  = lane >> 2, tig = lane & 3;
    int wm   = (warp & 3) * 32;
    int wn   = (warp >> 2) * 64;

    float acc[2][8][4];
    #pragma unroll
    for (int mt = 0; mt < 2; mt++)
        #pragma unroll
        for (int nt = 0; nt < 8; nt++)
            #pragma unroll
            for (int f = 0; f < 4; f++) acc[mt][nt][f] = 0.f;

    int nchunk = K >> 5;

    auto stage = [&](int st, int gk0){
        uint32_t sap = (uint32_t)__cvta_generic_to_shared(&sA[st][0]);
        uint32_t sbp = (uint32_t)__cvta_generic_to_shared(&sB[st][0]);
        #pragma unroll
        for (int j = 0; j < 2; j++){
            int c   = tid + j*256;
            int row = c >> 2;
            int kq  = c & 3;
            int gr  = brow + row;
            cph16(sap + (uint32_t)(row*80 + kq*16),
                  A + (size_t)gr*lda + gk0 + kq*8, gr < Nr);
        }
        #pragma unroll
        for (int j = 0; j < 2; j++){
            int c   = tid + j*256;
            int row = c >> 2;
            int kq  = c & 3;
            int gm  = bcol + row;
            cph16(sbp + (uint32_t)(row*80 + kq*16),
                  Bm + (size_t)gm*ldb + gk0 + kq*8, gm < Mc);
        }
    };

    stage(0, 0);
    asm volatile("cp.async.commit_group;");

    for (int kc = 0; kc < nchunk; kc++){
        if (kc + 1 < nchunk){ stage((kc+1)&1, (kc+1)*32); }
        asm volatile("cp.async.commit_group;");
        asm volatile("cp.async.wait_group 1;");
        __syncthreads();

        const __half* sa = sA[kc & 1];
        const __half* sb = sB[kc & 1];
        #pragma unroll
        for (int ks = 0; ks < 32; ks += 16){
            uint32_t a[2][4], b[8][2];
            #pragma unroll
            for (int mt = 0; mt < 2; mt++){
                int rb = wm + mt*16;
                a[mt][0] = *(const uint32_t*)&sa[(rb+gid  )*40 + ks + 2*tig    ];
                a[mt][1] = *(const uint32_t*)&sa[(rb+gid+8)*40 + ks + 2*tig    ];
                a[mt][2] = *(const uint32_t*)&sa[(rb+gid  )*40 + ks + 2*tig + 8];
                a[mt][3] = *(const uint32_t*)&sa[(rb+gid+8)*40 + ks + 2*tig + 8];
            }
            #pragma unroll
            for (int nt = 0; nt < 8; nt++){
                int cb = wn + nt*8;
                b[nt][0] = *(const uint32_t*)&sb[(cb+gid)*40 + ks + 2*tig    ];
                b[nt][1] = *(const uint32_t*)&sb[(cb+gid)*40 + ks + 2*tig + 8];
            }
            #pragma unroll
            for (int mt = 0; mt < 2; mt++)
                #pragma unroll
                for (int nt = 0; nt < 8; nt++)
                    asm volatile(
                        "mma.sync.aligned.m16n8k16.row.col.f32.f16.f16.f32 "
                        "{%0,%1,%2,%3}, {%4,%5,%6,%7}, {%8,%9}, {%0,%1,%2,%3};"
                        : "+f"(acc[mt][nt][0]), "+f"(acc[mt][nt][1]),
                          "+f"(acc[mt][nt][2]), "+f"(acc[mt][nt][3])
                        : "r"(a[mt][0]), "r"(a[mt][1]), "r"(a[mt][2]), "r"(a[mt][3]),
                          "r"(b[nt][0]), "r"(b[nt][1]));
        }
        __syncthreads();
    }

    #pragma unroll
    for (int mt = 0; mt < 2; mt++){
        #pragma unroll
        for (int half = 0; half < 2; half++){
            int r = brow + wm + mt*16 + gid + half*8;
            float rs = 1.f;
            if (rowscale && r < Nr){
                float dv = rowscale[r];
                rs = (rsMode == 1) ? ((dv == 0.f) ? 1.f : 1.f/dv)
                   : (rsMode == 2) ? rsqrtf(fmaxf(dv, 1.f)) : dv;
            }
            float es = 0.f;
            if (r < Nr){
                #pragma unroll
                for (int nt = 0; nt < 8; nt++){
                    int c0 = bcol + wn + nt*8 + tig*2;
                    #pragma unroll
                    for (int jj = 0; jj < 2; jj++){
                        int cm = c0 + jj;
                        if (cm >= Mc) continue;
                        float v = acc[mt][nt][half*2 + jj] * rs;
                        if (colscale) v *= colscale[cm];
                        if (bias) v += bias[cm];
                        if (accum) v += C[(size_t)r*ldc + cm];
                        C[(size_t)r*ldc + cm] = v;
                        if (expsum) es += expf(v - 12.f);
                    }
                }
            }
            if (expsum){
                es += __shfl_xor_sync(0xffffffffu, es, 1);
                es += __shfl_xor_sync(0xffffffffu, es, 2);
                if (tig == 0 && r < Nr) atomicAdd(&expsum[r], es);
            }
        }
    }
}

// ---------------- group-local edge kernels (atomic-free) ----------------------
#define EDGEB_SMEM ((2*NPGc*Dd + 2*64)*4)
__global__ void k_edgeB_grp(const int* __restrict__ src, const int* __restrict__ dst,
                            const float* __restrict__ w, const float* __restrict__ feat,
                            __half* __restrict__ num1h, __half* __restrict__ num2h,
                            float* __restrict__ den1, float* __restrict__ den2){
    extern __shared__ float sm[];
    float* n1s = sm;
    float* n2s = sm + NPGc*Dd;
    float* d1s = sm + 2*NPGc*Dd;
    float* d2s = d1s + 64;
    int b = blockIdx.x, d = threadIdx.x;
    for (int i = d; i < NPGc*Dd; i += 128){ n1s[i] = 0.f; n2s[i] = 0.f; }
    if (d < NPGc){ d1s[d] = 0.f; d2s[d] = 0.f; }
    __syncthreads();
    int nb = b*NPGc, eb = b*EPGc;
    for (int e = 0; e < EPGc; e++){
        int ge = eb + e;
        int s = src[ge] - nb, t = dst[ge] - nb;
        float ww = w[ge];
        n1s[t*Dd + d] += feat[(size_t)(nb+s)*Dd + d]*ww;
        n2s[s*Dd + d] += feat[(size_t)(nb+t)*Dd + d]*ww;
        if (d == 0) d1s[t] += ww;
        if (d == 32) d2s[s] += ww;
    }
    __syncthreads();
    for (int i = 0; i < NPGc; i++){
        num1h[(size_t)(nb+i)*Dd + d] = __float2half_rn(n1s[i*Dd + d]);
        num2h[(size_t)(nb+i)*Dd + d] = __float2half_rn(n2s[i*Dd + d]);
    }
    if (d < NPGc){ den1[nb+d] = d1s[d]; den2[nb+d] = d2s[d]; }
}

#define AGG2_SMEM ((2*NPGc*Dd + 64 + 64)*4)
__global__ void k_agg2_grp(const int* __restrict__ src, const int* __restrict__ dst,
                           const float* __restrict__ edge_t, const float* __restrict__ node_t,
                           const float* __restrict__ tend, int kstep,
                           const float* __restrict__ x, const float* __restrict__ h,
                           __half* __restrict__ aggx, __half* __restrict__ aggh,
                           float* __restrict__ emf, float* __restrict__ deg){
    extern __shared__ float sm[];
    float* ax = sm;
    float* ah = sm + NPGc*Dd;
    float* dg = sm + 2*NPGc*Dd;
    float* me = dg + 64;
    int b = blockIdx.x, d = threadIdx.x;
    for (int i = d; i < NPGc*Dd; i += 128){ ax[i] = 0.f; ah[i] = 0.f; }
    if (d < NPGc) dg[d] = 0.f;
    __syncthreads();
    int nb = b*NPGc, eb = b*EPGc;
    if (d < EPGc){
        int ge = eb + d;
        float dt = tend[0] / (float)NSPLITS;
        float t = (float)kstep * dt;
        int s = src[ge] - nb, tt = dst[ge] - nb;
        float m = (edge_t[ge] <= t && node_t[nb+s] >= t && node_t[nb+tt] >= t && s != tt)
                  ? 1.f : 0.f;
        me[d] = m; emf[ge] = m;
        if (m > 0.f){ atomicAdd(&dg[s], 1.f); atomicAdd(&dg[tt], 1.f); }
    }
    __syncthreads();
    for (int e = 0; e < EPGc; e++){
        if (me[e] == 0.f) continue;
        int ge = eb + e;
        int s = src[ge] - nb, t = dst[ge] - nb;
        float ds  = rsqrtf(fmaxf(dg[s], 1.f));
        float dt_ = rsqrtf(fmaxf(dg[t], 1.f));
        float xs = x[(size_t)(nb+s)*Dd + d], xt = x[(size_t)(nb+t)*Dd + d];
        float hs = h[(size_t)(nb+s)*Dd + d], ht = h[(size_t)(nb+t)*Dd + d];
        ax[t*Dd + d] += xs*ds;  ax[s*Dd + d] += xt*dt_;
        ah[t*Dd + d] += hs*ds;  ah[s*Dd + d] += ht*dt_;
    }
    __syncthreads();
    for (int i = 0; i < NPGc; i++){
        aggx[(size_t)(nb+i)*Dd + d] = __float2half_rn(ax[i*Dd + d]);
        aggh[(size_t)(nb+i)*Dd + d] = __float2half_rn(ah[i*Dd + d]);
    }
    if (d < NPGc) deg[nb+d] = dg[d];
}

// single aggregate of rh (fp32 in, fp16 out) — R12 config
#define AGG1_SMEM ((NPGc*Dd + 64 + 64)*4)
__global__ void k_agg1_grp(const int* __restrict__ src, const int* __restrict__ dst,
                           const float* __restrict__ emf, const float* __restrict__ deg,
                           const float* __restrict__ rh, __half* __restrict__ agg){
    extern __shared__ float sm[];
    float* as = sm;
    float* dg = sm + NPGc*Dd;
    float* me = dg + 64;
    int b = blockIdx.x, d = threadIdx.x;
    for (int i = d; i < NPGc*Dd; i += 128) as[i] = 0.f;
    int nb = b*NPGc, eb = b*EPGc;
    if (d < NPGc) dg[d] = deg[nb+d];
    if (d < EPGc) me[d] = emf[eb+d];
    __syncthreads();
    for (int e = 0; e < EPGc; e++){
        if (me[e] == 0.f) continue;
        int ge = eb + e;
        int s = src[ge] - nb, t = dst[ge] - nb;
        float ds  = rsqrtf(fmaxf(dg[s], 1.f));
        float dt_ = rsqrtf(fmaxf(dg[t], 1.f));
        as[t*Dd + d] += rh[(size_t)(nb+s)*Dd + d]*ds;
        as[s*Dd + d] += rh[(size_t)(nb+t)*Dd + d]*dt_;
    }
    __syncthreads();
    for (int i = 0; i < NPGc; i++)
        agg[(size_t)(nb+i)*Dd + d] = __float2half_rn(as[i*Dd + d]);
}

// ---------------- conversions (emb + all weights in ONE launch) ---------------
// ranges in float4 units: emb 3,276,800 | gwih 24,576 | W1 4,096 | W2 4,096 | gwhh 12,288
__global__ void k_cvtw(const float* emb, __half* emb16,
                       const float* gwih, __half* gwih16,
                       const float* W1, __half* w116,
                       const float* W2, __half* w216,
                       const float* gwhh, __half* gwhh16){
    int i = blockIdx.x*256 + threadIdx.x;
    const float* in; __half* out; int j;
    if (i < 3276800){ in = emb; out = emb16; j = i; }
    else if (i < 3301376){ in = gwih; out = gwih16; j = i - 3276800; }
    else if (i < 3305472){ in = W1; out = w116; j = i - 3301376; }
    else if (i < 3309568){ in = W2; out = w216; j = i - 3305472; }
    else if (i < 3321856){ in = gwhh; out = gwhh16; j = i - 3309568; }
    else return;
    float4 v = ((const float4*)in)[j];
    ((__half2*)out)[2*j]   = __floats2half2_rn(v.x, v.y);
    ((__half2*)out)[2*j+1] = __floats2half2_rn(v.z, v.w);
}

__global__ void k_cvt2(const float* a, __half* ah, int na4,
                       const float* b, __half* bh, int nb4){
    int i = blockIdx.x*256 + threadIdx.x;
    const float* in; __half* out; int j;
    if (i < na4){ in = a; out = ah; j = i; }
    else if (i - na4 < nb4){ in = b; out = bh; j = i - na4; }
    else return;
    float4 v = ((const float4*)in)[j];
    ((__half2*)out)[2*j]   = __floats2half2_rn(v.x, v.y);
    ((__half2*)out)[2*j+1] = __floats2half2_rn(v.z, v.w);
}

// ---------------- helpers -----------------------------------------------------
__global__ void k_gather_norm(const float* __restrict__ emb, const int* __restrict__ iid,
                              float* __restrict__ out, __half* __restrict__ out16){
    int n = blockIdx.x, d = threadIdx.x;
    float v = emb[(size_t)iid[n]*Dd + d];
    float s = v*v;
    #pragma unroll
    for (int o = 16; o; o >>= 1) s += __shfl_xor_sync(0xffffffffu, s, o);
    __shared__ float sh[4];
    if ((d & 31) == 0) sh[d>>5] = s;
    __syncthreads();
    float tot = sh[0]+sh[1]+sh[2]+sh[3];
    float nf = v / fmaxf(sqrtf(tot), 1e-12f);
    out[(size_t)n*Dd + d] = nf;
    out16[(size_t)n*Dd + d] = __float2half_rn(nf);
}

__global__ void k_row_norm_h(const float* __restrict__ in, float* __restrict__ out,
                             __half* __restrict__ out16){
    int n = blockIdx.x, d = threadIdx.x;
    float v = in[(size_t)n*Dd + d];
    float s = v*v;
    #pragma unroll
    for (int o = 16; o; o >>= 1) s += __shfl_xor_sync(0xffffffffu, s, o);
    __shared__ float sh[4];
    if ((d & 31) == 0) sh[d>>5] = s;
    __syncthreads();
    float tot = sh[0]+sh[1]+sh[2]+sh[3];
    float nf = v / fmaxf(sqrtf(tot), 1e-12f);
    out[(size_t)n*Dd + d] = nf;
    if (out16) out16[(size_t)n*Dd + d] = __float2half_rn(nf);
}

__global__ void k_emb_scale(const float* __restrict__ emb, float* __restrict__ sc){
    int v = blockIdx.x, d = threadIdx.x;
    float x = emb[(size_t)v*Dd + d];
    float s = x*x;
    #pragma unroll
    for (int o = 16; o; o >>= 1) s += __shfl_xor_sync(0xffffffffu, s, o);
    __shared__ float sh[4];
    if ((d & 31) == 0) sh[d>>5] = s;
    __syncthreads();
    if (d == 0){
        float tot = sh[0]+sh[1]+sh[2]+sh[3];
        sc[v] = NSCALE / fmaxf(sqrtf(tot), 1e-12f);
    }
}

// pack transposed weights + biases + zero expsum/tend (all fused)
__global__ void k_pack(const float* Wxr, const float* Wxz, const float* Wxh,
                       const float* Whr, const float* Whz, const float* Whh,
                       const float* Wu, const float* Wv, const float* W_sr,
                       const float* bxr, const float* bxz, const float* bxh,
                       const float* bhr, const float* bhz,
                       __half* WcxT, __half* WchT, __half* WhhT,
                       __half* WuT, __half* WvT, __half* WsrT,
                       float* bcx, float* bch,
                       float* expsum, float* tend){
    int i = blockIdx.x*256 + threadIdx.x;
    if (i < 49152){
        int j = i >> 7, k = i & 127;
        const float* W = (j < 128) ? Wxr : ((j < 256) ? Wxz : Wxh);
        WcxT[i] = __float2half_rn(W[k*128 + (j & 127)]);
    } else if (i < 81920){
        int t = i - 49152;
        int j = t >> 7, k = t & 127;
        const float* W = (j < 128) ? Whr : Whz;
        WchT[t] = __float2half_rn(W[k*128 + (j & 127)]);
    } else if (i < 98304){
        int t = i - 81920;
        int j = t >> 7, k = t & 127;
        WhhT[t] = __float2half_rn(Whh[k*128 + j]);
    } else if (i < 114688){
        int t = i - 98304;
        int j = t >> 7, k = t & 127;
        WuT[t] = __float2half_rn(Wu[k*128 + j]);
    } else if (i < 131072){
        int t = i - 114688;
        int j = t >> 7, k = t & 127;
        WvT[t] = __float2half_rn(Wv[k*128 + j]);
    } else if (i < 163840){
        int t = i - 131072;
        int j = t >> 8, k = t & 255;
        WsrT[t] = __float2half_rn(W_sr[k*128 + j]);
    } else if (i < 164224){
        int j = i - 163840;
        bcx[j] = (j < 128) ? bxr[j] : ((j < 256) ? bxz[j-128] : bxh[j-256]);
    } else if (i < 164480){
        int j = i - 164224;
        bch[j] = (j < 128) ? bhr[j] : bhz[j-128];
    } else if (i < 164480 + Bq){
        expsum[i - 164480] = 0.f;
    } else if (i == 164480 + Bq){
        tend[0] = 0.f;
    }
}

// ---------------- fused GRU + l2norm + copy to x,h ----------------------------
__global__ void k_gru_norm(const float* __restrict__ gi, const float* __restrict__ gh,
                           float* __restrict__ feat, float* __restrict__ x,
                           float* __restrict__ h){
    int n = blockIdx.x, d = threadIdx.x;
    size_t b3 = (size_t)n*384 + d;
    float ir = gi[b3], iz = gi[b3+128], ig = gi[b3+256];
    float hr = gh[b3], hz = gh[b3+128], hg = gh[b3+256];
    float r = 1.f/(1.f + expf(-(ir + hr)));
    float z = 1.f/(1.f + expf(-(iz + hz)));
    float g = tanhf(ig + r*hg);
    size_t i = (size_t)n*Dd + d;
    float f = (1.f - z)*g + z*feat[i];
    float s = f*f;
    #pragma unroll
    for (int o = 16; o; o >>= 1) s += __shfl_xor_sync(0xffffffffu, s, o);
    __shared__ float sh[4];
    if ((d & 31) == 0) sh[d>>5] = s;
    __syncthreads();
    float tot = sh[0]+sh[1]+sh[2]+sh[3];
    float nf = f / fmaxf(sqrtf(tot), 1e-12f);
    feat[i] = nf; x[i] = nf; h[i] = nf;
}

__global__ void k_tmax(const float* __restrict__ et, float* tend){
    int i = blockIdx.x*256 + threadIdx.x;
    float v = (i < EE) ? et[i] : 0.f;
    #pragma unroll
    for (int o = 16; o; o >>= 1) v = fmaxf(v, __shfl_xor_sync(0xffffffffu, v, o));
    if ((threadIdx.x & 31) == 0) atomicMax((int*)tend, __float_as_int(v));
}

__global__ void k_rz(const float* __restrict__ Gx, const float* __restrict__ Gh,
                     const float* __restrict__ h, float* __restrict__ zz,
                     float* __restrict__ rh){
    int i = blockIdx.x*256 + threadIdx.x;
    if (i >= ND) return;
    int n = i >> 7, d = i & 127;
    size_t bx = (size_t)n*384 + d, bh = (size_t)n*256 + d;
    float rr = 1.f/(1.f + expf(-(Gx[bx]     + Gh[bh]    )));
    float zv = 1.f/(1.f + expf(-(Gx[bx+128] + Gh[bh+128])));
    zz[i] = zv;
    rh[i] = rr * h[i];
}

__global__ void k_upd(const float* __restrict__ Gx, const float* __restrict__ t2,
                      const float* __restrict__ zz, const float* __restrict__ node_t,
                      const float* __restrict__ tend, int kstep, float* __restrict__ h){
    int i = blockIdx.x*256 + threadIdx.x;
    if (i >= ND) return;
    int n = i >> 7, d = i & 127;
    float uu = tanhf(Gx[(size_t)n*384 + 256 + d] + t2[i]);
    float dt = tend[0] / (float)NSPLITS;
    float t = (float)kstep * dt;
    float hv = h[i];
    float dh = (node_t[n] >= t) ? (1.f - zz[i])*(uu - hv) : 0.f;
    h[i] = hv + dt*dh;
}

// ---------------- attention readout (writes f32 + fp16 cc) --------------------
__global__ void k_attn(const float* __restrict__ feat, const float* __restrict__ q,
                       const float* __restrict__ fwu, const float* __restrict__ We,
                       float* __restrict__ cc, __half* __restrict__ cc16){
    int b = blockIdx.x, d = threadIdx.x;
    __shared__ float e_sh[NPGc];
    __shared__ float red[4];
    const float* fb  = feat + (size_t)b*NPGc*Dd;
    const float* fwb = fwu  + (size_t)b*NPGc*Dd;
    float qd = q[(size_t)b*Dd + d];
    float wed = We[d];
    for (int i = 0; i < NPGc; i++){
        float s = (1.f/(1.f + expf(-(fwb[(size_t)i*Dd + d] + qd)))) * wed;
        #pragma unroll
        for (int o = 16; o; o >>= 1) s += __shfl_xor_sync(0xffffffffu, s, o);
        if ((d & 31) == 0) red[d>>5] = s;
        __syncthreads();
        if (d == 0) e_sh[i] = red[0]+red[1]+red[2]+red[3];
        __syncthreads();
    }
    float mx = -1e30f;
    for (int i = 0; i < NPGc; i++) mx = fmaxf(mx, e_sh[i]);
    float sm = 0.f;
    for (int i = 0; i < NPGc; i++) sm += expf(e_sh[i] - mx);
    float srg = 0.f;
    for (int i = 0; i < NPGc; i++) srg += fb[(size_t)i*Dd + d]*(expf(e_sh[i] - mx)/sm);
    float last = fb[(size_t)(NPGc-1)*Dd + d];
    cc[(size_t)b*2*Dd + d]      = last;
    cc[(size_t)b*2*Dd + Dd + d] = srg;
    cc16[(size_t)b*2*Dd + d]      = __float2half_rn(last);
    cc16[(size_t)b*2*Dd + Dd + d] = __float2half_rn(srg);
}

// float4-vectorized subtract (Vv divisible by 4)
__global__ void k_sub(float* __restrict__ out, const float* __restrict__ expsum){
    int v4 = blockIdx.x*256 + threadIdx.x;
    int b = blockIdx.y;
    if (v4 >= Vv/4) return;
    float l = 12.f + logf(expsum[b]);
    float4* p = (float4*)(out + (size_t)b*Vv) + v4;
    float4 x = *p;
    x.x -= l; x.y -= l; x.z -= l; x.w -= l;
    *p = x;
}

// ---------------- host orchestration ------------------------------------------
static inline void gemm16(const __half* A, int lda, const __half* B, int ldb,
                          const float* bias, const float* cs,
                          const float* rs, int rsMode,
                          float* C, int ldc, float* expsum,
                          int Nr, int Mc, int K, int accum = 0){
    dim3 grid((Nr + 127)/128, (Mc + 127)/128);
    k_gemm_h<<<grid, 256>>>(A, lda, B, ldb, bias, cs, rs, rsMode,
                            C, ldc, expsum, Nr, Mc, K, accum);
}

extern "C" void kernel_launch(void* const* d_in, const int* in_sizes, int n_in,
                              void* d_out, int out_size)
{
    const int*   iid    = (const int*)  d_in[0];
    const int*   src    = (const int*)  d_in[1];
    const int*   dst    = (const int*)  d_in[2];
    const float* edge_w = (const float*)d_in[3];
    const float* edge_t = (const float*)d_in[4];
    const float* node_t = (const float*)d_in[5];
    const float* emb    = (const float*)d_in[6];
    const float* W1     = (const float*)d_in[7];
    const float* W2     = (const float*)d_in[8];
    const float* gw_ih  = (const float*)d_in[9];
    const float* gw_hh  = (const float*)d_in[10];
    const float* gb_ih  = (const float*)d_in[11];
    const float* gb_hh  = (const float*)d_in[12];
    const float* Wxr = (const float*)d_in[13]; const float* bxr = (const float*)d_in[14];
    const float* Wxz = (const float*)d_in[15]; const float* bxz = (const float*)d_in[16];
    const float* Wxh = (const float*)d_in[17]; const float* bxh = (const float*)d_in[18];
    const float* Whr = (const float*)d_in[19]; const float* bhr = (const float*)d_in[20];
    const float* Whz = (const float*)d_in[21]; const float* bhz = (const float*)d_in[22];
    const float* Whh = (const float*)d_in[23]; const float* bhh = (const float*)d_in[24];
    const float* Wu  = (const float*)d_in[25];
    const float* Wv  = (const float*)d_in[26];
    const float* bv  = (const float*)d_in[27];
    const float* We  = (const float*)d_in[28];
    const float* W_sr= (const float*)d_in[29];
    float* out = (float*)d_out;

    static int s_attr_done = 0;
    if (!s_attr_done){
        cudaFuncSetAttribute(k_edgeB_grp, cudaFuncAttributeMaxDynamicSharedMemorySize, EDGEB_SMEM);
        cudaFuncSetAttribute(k_agg2_grp,  cudaFuncAttributeMaxDynamicSharedMemorySize, AGG2_SMEM);
        cudaFuncSetAttribute(k_agg1_grp,  cudaFuncAttributeMaxDynamicSharedMemorySize, AGG1_SMEM);
        s_attr_done = 1;
    }

    float *p_feat,*p_nv,*p_gi,*p_gh,*p_x,*p_h,*p_t1,*p_t2,*p_rh,*p_zz;
    float *p_emf,*p_tend,*p_sc,*p_q,*p_cc,*p_sr,*p_bcx,*p_bch,*p_expsum;
    __half *p_agg16,*p_feat16,*p_cc16,*p_sr16,*p_emb16,*p_gwih16,*p_w116,*p_w216;
    __half *p_gwhh16,*p_wcxT16,*p_wchT16,*p_whhT16,*p_wuT16,*p_wvT16,*p_wsrT16;
    __half *p_wc1T16,*p_wc2T16;
    cudaGetSymbolAddress((void**)&p_feat, g_feat);
    cudaGetSymbolAddress((void**)&p_nv,   g_nv);
    cudaGetSymbolAddress((void**)&p_gi,   g_gi);
    cudaGetSymbolAddress((void**)&p_gh,   g_gh);
    cudaGetSymbolAddress((void**)&p_x,    g_x);
    cudaGetSymbolAddress((void**)&p_h,    g_h);
    cudaGetSymbolAddress((void**)&p_t1,   g_t1);
    cudaGetSymbolAddress((void**)&p_t2,   g_t2);
    cudaGetSymbolAddress((void**)&p_rh,   g_rh);
    cudaGetSymbolAddress((void**)&p_zz,   g_zz);
    cudaGetSymbolAddress((void**)&p_emf,  g_emf);
    cudaGetSymbolAddress((void**)&p_tend, g_tend);
    cudaGetSymbolAddress((void**)&p_sc,   g_sc);
    cudaGetSymbolAddress((void**)&p_q,    g_q);
    cudaGetSymbolAddress((void**)&p_cc,   g_cc);
    cudaGetSymbolAddress((void**)&p_sr,   g_sr);
    cudaGetSymbolAddress((void**)&p_bcx,  g_bcx);
    cudaGetSymbolAddress((void**)&p_bch,  g_bch);
    cudaGetSymbolAddress((void**)&p_expsum, g_expsum);
    cudaGetSymbolAddress((void**)&p_agg16, g_agg16);
    cudaGetSymbolAddress((void**)&p_feat16,g_feat16);
    cudaGetSymbolAddress((void**)&p_cc16, g_cc16);
    cudaGetSymbolAddress((void**)&p_sr16, g_sr16);
    cudaGetSymbolAddress((void**)&p_emb16,g_emb16);
    cudaGetSymbolAddress((void**)&p_gwih16,g_gwih16);
    cudaGetSymbolAddress((void**)&p_w116, g_w116);
    cudaGetSymbolAddress((void**)&p_w216, g_w216);
    cudaGetSymbolAddress((void**)&p_gwhh16,g_gwhh16);
    cudaGetSymbolAddress((void**)&p_wcxT16,g_wcxT16);
    cudaGetSymbolAddress((void**)&p_wchT16,g_wchT16);
    cudaGetSymbolAddress((void**)&p_whhT16,g_whhT16);
    cudaGetSymbolAddress((void**)&p_wuT16, g_wuT16);
    cudaGetSymbolAddress((void**)&p_wvT16, g_wvT16);
    cudaGetSymbolAddress((void**)&p_wsrT16,g_wsrT16);
    cudaGetSymbolAddress((void**)&p_wc1T16,g_wc1T16);
    cudaGetSymbolAddress((void**)&p_wc2T16,g_wc2T16);

    __half* p_aggx16 = p_agg16;
    __half* p_aggh16 = p_agg16 + ND;
    __half* p_aggrh16= p_agg16 + 2*ND;
    float* p_den1  = p_nv;
    float* p_den2  = p_nv + NN;
    float* p_deg   = p_nv + 2*NN;

    // ---- Stage A + weight prep ----
    k_gather_norm<<<NN, 128>>>(emb, iid, p_feat, p_feat16);
    k_emb_scale<<<Vv, 128>>>(emb, p_sc);
    k_cvtw<<<(3321856 + 255)/256, 256>>>(emb, p_emb16, gw_ih, p_gwih16,
                                         W1, p_w116, W2, p_w216, gw_hh, p_gwhh16);
    k_pack<<<(164480 + Bq + 1 + 255)/256, 256>>>(Wxr, Wxz, Wxh, Whr, Whz, Whh, Wu, Wv, W_sr,
                                      bxr, bxz, bxh, bhr, bhz,
                                      p_wcxT16, p_wchT16, p_whhT16, p_wuT16, p_wvT16,
                                      p_wsrT16, p_bcx, p_bch, p_expsum, p_tend);
    gemm16(p_gwih16,       256, p_w116, 128, nullptr, nullptr, nullptr, 0,
           p_t1, 128, nullptr, 384, 128, 128);
    gemm16(p_gwih16 + 128, 256, p_w216, 128, nullptr, nullptr, nullptr, 0,
           p_t2, 128, nullptr, 384, 128, 128);
    k_cvt2<<<(2*12288 + 255)/256, 256>>>(p_t1, p_wc1T16, 12288, p_t2, p_wc2T16, 12288);

    // ---- Stage B ----
    k_edgeB_grp<<<Bq, 128, EDGEB_SMEM>>>(src, dst, edge_w, p_feat,
                                         p_aggx16, p_aggh16, p_den1, p_den2);
    k_tmax<<<(EE+255)/256, 256>>>(edge_t, p_tend);

    // ---- Stage C ----
    gemm16(p_aggx16, Dd, p_wc1T16, 128, gb_ih,  nullptr, p_den1, 1,
           p_gi, 384, nullptr, NN, 384, Dd, 0);
    gemm16(p_aggh16, Dd, p_wc2T16, 128, nullptr, nullptr, p_den2, 1,
           p_gi, 384, nullptr, NN, 384, Dd, 1);
    gemm16(p_feat16, Dd, p_gwhh16, 128, gb_hh, nullptr, nullptr, 0,
           p_gh, 384, nullptr, NN, 384, Dd, 0);

    // ---- Stage D ----
    k_gru_norm<<<NN, 128>>>(p_gi, p_gh, p_feat, p_x, p_h);

    // ---- Stage E: ODE (exact R12 structure: 7 launches/step) ----
    for (int k = 0; k < NSPLITS; k++){
        k_agg2_grp<<<Bq, 128, AGG2_SMEM>>>(src, dst, edge_t, node_t, p_tend, k,
                                           p_x, p_h, p_aggx16, p_aggh16, p_emf, p_deg);
        gemm16(p_aggx16, Dd, p_wcxT16, 128, p_bcx, nullptr, p_deg, 2,
               p_gi, 384, nullptr, NN, 384, Dd, 0);
        gemm16(p_aggh16, Dd, p_wchT16, 128, p_bch, nullptr, p_deg, 2,
               p_gh, 256, nullptr, NN, 256, Dd, 0);
        k_rz<<<(ND+255)/256, 256>>>(p_gi, p_gh, p_h, p_zz, p_rh);
        k_agg1_grp<<<Bq, 128, AGG1_SMEM>>>(src, dst, p_emf, p_deg, p_rh, p_aggrh16);
        gemm16(p_aggrh16, Dd, p_whhT16, 128, bhh, nullptr, p_deg, 2,
               p_t2, Dd, nullptr, NN, Dd, Dd, 0);
        k_upd<<<(ND+255)/256, 256>>>(p_gi, p_t2, p_zz, node_t, p_tend, k, p_h);
    }
    k_row_norm_h<<<NN, 128>>>(p_h, p_feat, p_feat16);

    // ---- Stage F ----
    gemm16(p_feat16, Dd, p_wuT16, 128, nullptr, nullptr, nullptr, 0,
           p_t1, Dd, nullptr, NN, Dd, Dd, 0);
    gemm16(p_feat16 + (size_t)(NPGc-1)*Dd, NPGc*Dd, p_wvT16, 128, bv, nullptr, nullptr, 0,
           p_q, Dd, nullptr, Bq, Dd, Dd, 0);
    k_attn<<<Bq, 128>>>(p_feat, p_q, p_t1, We, p_cc, p_cc16);
    gemm16(p_cc16, 2*Dd, p_wsrT16, 256, nullptr, nullptr, nullptr, 0,
           p_sr, Dd, nullptr, Bq, Dd, 2*Dd, 0);
    k_row_norm_h<<<Bq, 128>>>(p_sr, p_sr, p_sr16);

    // ---- Stage G ----
    gemm16(p_sr16, Dd, p_emb16, 128, nullptr, p_sc, nullptr, 0,
           out, Vv, p_expsum, Bq, Vv, Dd, 0);
    k_sub<<<dim3((Vv/4+255)/256, Bq), 256>>>(out, p_expsum);
}

// round 17
// speedup vs baseline: 1.1585x; 1.0010x over previous
#include <cuda_runtime.h>
#include <cuda_fp16.h>
#include <math.h>
#include <stdint.h>

// Problem constants
#define Bq   512
#define NPGc 50
#define EPGc 60
#define Dd   128
#define Vv   100000
#define NSPLITS 4
#define NSCALE 12.0f
#define NN   (Bq*NPGc)   // 25600 nodes
#define EE   (Bq*EPGc)   // 30720 edges
#define ND   (NN*Dd)

// ---------------- scratch (device globals) ----------------------------------
__device__ float g_feat[ND];
__device__ float g_nv[3*NN];       // den1 | den2 | deg
__device__ float g_gi[NN*384];     // gi / Gx
__device__ float g_gh[NN*384];     // gh / Gh
__device__ float g_x[ND];
__device__ float g_h[ND];
__device__ float g_t1[ND];
__device__ float g_t2[ND];
__device__ float g_rh[ND];
__device__ float g_zz[ND];
__device__ float g_emf[EE];
__device__ float g_tend[1];
__device__ float g_sc[Vv];
__device__ float g_q[Bq*Dd];
__device__ float g_cc[Bq*2*Dd];
__device__ float g_sr[Bq*Dd];
__device__ float g_expsum[Bq];
// fp16 mirrors ---------------------------------------------------------------
__device__ __half g_agg16[3*ND];   // aggx | aggh | aggrh (also num1|num2)
__device__ __half g_feat16[ND];
__device__ __half g_cc16[Bq*2*Dd];
__device__ __half g_sr16[Bq*Dd];
__device__ __half g_emb16[(size_t)Vv*Dd];
__device__ __half g_gwih16[384*256];
__device__ __half g_w116[128*128];
__device__ __half g_w216[128*128];
__device__ __half g_gwhh16[384*128];
__device__ __half g_wcxT16[384*128];  // [Wxr|Wxz|Wxh]^T
__device__ __half g_wchT16[256*128];  // [Whr|Whz]^T
__device__ __half g_whhT16[128*128];
__device__ __half g_wuT16 [128*128];
__device__ __half g_wvT16 [128*128];
__device__ __half g_wsrT16[128*256];
__device__ __half g_wc1T16[384*128];
__device__ __half g_wc2T16[384*128];
__device__ float g_bcx[384];
__device__ float g_bch[256];

// ---------------- fp16 tensor-core GEMM (R16 config + LDSM fragment loads) ----
// C[r,n] (+= if accum) = RS(r) * (sum_k A[r,k]*B[n,k]) * colscale[n] + bias[n]
// rsMode: 0 = rowscale[r]; 1 = (den==0?1:1/den); 2 = rsqrt(max(deg,1)).
// expsum: accumulate sum_n exp(v-12) per row (logits mode).
__device__ __forceinline__ void cph16(uint32_t dst, const __half* src, bool pred){
    int sz = pred ? 16 : 0;
    asm volatile("cp.async.cg.shared.global [%0], [%1], 16, %2;"
                 :: "r"(dst), "l"(src), "r"(sz));
}

__global__ __launch_bounds__(256)
void k_gemm_h(const __half* __restrict__ A, int lda,
              const __half* __restrict__ Bm, int ldb,
              const float* __restrict__ bias,
              const float* __restrict__ colscale,
              const float* __restrict__ rowscale, int rsMode,
              float* __restrict__ C, int ldc,
              float* __restrict__ expsum,
              int Nr, int Mc, int K, int accum)
{
    __shared__ __half sA[2][128*40];   // [row][k], row stride 40 halves (80 B)
    __shared__ __half sB[2][128*40];
    int brow = blockIdx.x*128;
    int bcol = blockIdx.y*128;
    int tid  = threadIdx.x;
    int warp = tid >> 5, lane = tid & 31;
    int gid  = lane >> 2, tig = lane & 3;
    int wm   = (warp & 3) * 32;
    int wn   = (warp >> 2) * 64;

    float acc[2][8][4];
    #pragma unroll
    for (int mt = 0; mt < 2; mt++)
        #pragma unroll
        for (int nt = 0; nt < 8; nt++)
            #pragma unroll
            for (int f = 0; f < 4; f++) acc[mt][nt][f] = 0.f;

    int nchunk = K >> 5;

    auto stage = [&](int st, int gk0){
        uint32_t sap = (uint32_t)__cvta_generic_to_shared(&sA[st][0]);
        uint32_t sbp = (uint32_t)__cvta_generic_to_shared(&sB[st][0]);
        #pragma unroll
        for (int j = 0; j < 2; j++){
            int c   = tid + j*256;
            int row = c >> 2;
            int kq  = c & 3;
            int gr  = brow + row;
            cph16(sap + (uint32_t)(row*80 + kq*16),
                  A + (size_t)gr*lda + gk0 + kq*8, gr < Nr);
        }
        #pragma unroll
        for (int j = 0; j < 2; j++){
            int c   = tid + j*256;
            int row = c >> 2;
            int kq  = c & 3;
            int gm  = bcol + row;
            cph16(sbp + (uint32_t)(row*80 + kq*16),
                  Bm + (size_t)gm*ldb + gk0 + kq*8, gm < Mc);
        }
    };

    // ldmatrix per-lane byte offsets (lane-constant across the k loop)
    int lrow = lane & 7, lg = lane >> 3;
    uint32_t aoff[2], boff[4];
    #pragma unroll
    for (int mt = 0; mt < 2; mt++)
        aoff[mt] = (uint32_t)((wm + mt*16 + (lg & 1)*8 + lrow) * 80 + (lg >> 1)*16);
    #pragma unroll
    for (int p = 0; p < 4; p++)
        boff[p] = (uint32_t)((wn + p*16 + (lg >> 1)*8 + lrow) * 80 + (lg & 1)*16);

    stage(0, 0);
    asm volatile("cp.async.commit_group;");

    for (int kc = 0; kc < nchunk; kc++){
        if (kc + 1 < nchunk){ stage((kc+1)&1, (kc+1)*32); }
        asm volatile("cp.async.commit_group;");
        asm volatile("cp.async.wait_group 1;");
        __syncthreads();

        uint32_t saB = (uint32_t)__cvta_generic_to_shared(&sA[kc & 1][0]);
        uint32_t sbB = (uint32_t)__cvta_generic_to_shared(&sB[kc & 1][0]);
        #pragma unroll
        for (int ks = 0; ks < 32; ks += 16){
            uint32_t a[2][4], b[8][2];
            #pragma unroll
            for (int mt = 0; mt < 2; mt++){
                asm volatile(
                    "ldmatrix.sync.aligned.m8n8.x4.shared.b16 {%0,%1,%2,%3}, [%4];"
                    : "=r"(a[mt][0]), "=r"(a[mt][1]), "=r"(a[mt][2]), "=r"(a[mt][3])
                    : "r"(saB + aoff[mt] + (uint32_t)(ks*2)));
            }
            #pragma unroll
            for (int p = 0; p < 4; p++){
                asm volatile(
                    "ldmatrix.sync.aligned.m8n8.x4.shared.b16 {%0,%1,%2,%3}, [%4];"
                    : "=r"(b[2*p][0]), "=r"(b[2*p][1]), "=r"(b[2*p+1][0]), "=r"(b[2*p+1][1])
                    : "r"(sbB + boff[p] + (uint32_t)(ks*2)));
            }
            #pragma unroll
            for (int mt = 0; mt < 2; mt++)
                #pragma unroll
                for (int nt = 0; nt < 8; nt++)
                    asm volatile(
                        "mma.sync.aligned.m16n8k16.row.col.f32.f16.f16.f32 "
                        "{%0,%1,%2,%3}, {%4,%5,%6,%7}, {%8,%9}, {%0,%1,%2,%3};"
                        : "+f"(acc[mt][nt][0]), "+f"(acc[mt][nt][1]),
                          "+f"(acc[mt][nt][2]), "+f"(acc[mt][nt][3])
                        : "r"(a[mt][0]), "r"(a[mt][1]), "r"(a[mt][2]), "r"(a[mt][3]),
                          "r"(b[nt][0]), "r"(b[nt][1]));
        }
        __syncthreads();
    }

    #pragma unroll
    for (int mt = 0; mt < 2; mt++){
        #pragma unroll
        for (int half = 0; half < 2; half++){
            int r = brow + wm + mt*16 + gid + half*8;
            float rs = 1.f;
            if (rowscale && r < Nr){
                float dv = rowscale[r];
                rs = (rsMode == 1) ? ((dv == 0.f) ? 1.f : 1.f/dv)
                   : (rsMode == 2) ? rsqrtf(fmaxf(dv, 1.f)) : dv;
            }
            float es = 0.f;
            if (r < Nr){
                #pragma unroll
                for (int nt = 0; nt < 8; nt++){
                    int c0 = bcol + wn + nt*8 + tig*2;
                    #pragma unroll
                    for (int jj = 0; jj < 2; jj++){
                        int cm = c0 + jj;
                        if (cm >= Mc) continue;
                        float v = acc[mt][nt][half*2 + jj] * rs;
                        if (colscale) v *= colscale[cm];
                        if (bias) v += bias[cm];
                        if (accum) v += C[(size_t)r*ldc + cm];
                        C[(size_t)r*ldc + cm] = v;
                        if (expsum) es += expf(v - 12.f);
                    }
                }
            }
            if (expsum){
                es += __shfl_xor_sync(0xffffffffu, es, 1);
                es += __shfl_xor_sync(0xffffffffu, es, 2);
                if (tig == 0 && r < Nr) atomicAdd(&expsum[r], es);
            }
        }
    }
}

// ---------------- group-local edge kernels (atomic-free) ----------------------
#define EDGEB_SMEM ((2*NPGc*Dd + 2*64)*4)
__global__ void k_edgeB_grp(const int* __restrict__ src, const int* __restrict__ dst,
                            const float* __restrict__ w, const float* __restrict__ feat,
                            __half* __restrict__ num1h, __half* __restrict__ num2h,
                            float* __restrict__ den1, float* __restrict__ den2){
    extern __shared__ float sm[];
    float* n1s = sm;
    float* n2s = sm + NPGc*Dd;
    float* d1s = sm + 2*NPGc*Dd;
    float* d2s = d1s + 64;
    int b = blockIdx.x, d = threadIdx.x;
    for (int i = d; i < NPGc*Dd; i += 128){ n1s[i] = 0.f; n2s[i] = 0.f; }
    if (d < NPGc){ d1s[d] = 0.f; d2s[d] = 0.f; }
    __syncthreads();
    int nb = b*NPGc, eb = b*EPGc;
    for (int e = 0; e < EPGc; e++){
        int ge = eb + e;
        int s = src[ge] - nb, t = dst[ge] - nb;
        float ww = w[ge];
        n1s[t*Dd + d] += feat[(size_t)(nb+s)*Dd + d]*ww;
        n2s[s*Dd + d] += feat[(size_t)(nb+t)*Dd + d]*ww;
        if (d == 0) d1s[t] += ww;
        if (d == 32) d2s[s] += ww;
    }
    __syncthreads();
    for (int i = 0; i < NPGc; i++){
        num1h[(size_t)(nb+i)*Dd + d] = __float2half_rn(n1s[i*Dd + d]);
        num2h[(size_t)(nb+i)*Dd + d] = __float2half_rn(n2s[i*Dd + d]);
    }
    if (d < NPGc){ den1[nb+d] = d1s[d]; den2[nb+d] = d2s[d]; }
}

#define AGG2_SMEM ((2*NPGc*Dd + 64 + 64)*4)
__global__ void k_agg2_grp(const int* __restrict__ src, const int* __restrict__ dst,
                           const float* __restrict__ edge_t, const float* __restrict__ node_t,
                           const float* __restrict__ tend, int kstep,
                           const float* __restrict__ x, const float* __restrict__ h,
                           __half* __restrict__ aggx, __half* __restrict__ aggh,
                           float* __restrict__ emf, float* __restrict__ deg){
    extern __shared__ float sm[];
    float* ax = sm;
    float* ah = sm + NPGc*Dd;
    float* dg = sm + 2*NPGc*Dd;
    float* me = dg + 64;
    int b = blockIdx.x, d = threadIdx.x;
    for (int i = d; i < NPGc*Dd; i += 128){ ax[i] = 0.f; ah[i] = 0.f; }
    if (d < NPGc) dg[d] = 0.f;
    __syncthreads();
    int nb = b*NPGc, eb = b*EPGc;
    if (d < EPGc){
        int ge = eb + d;
        float dt = tend[0] / (float)NSPLITS;
        float t = (float)kstep * dt;
        int s = src[ge] - nb, tt = dst[ge] - nb;
        float m = (edge_t[ge] <= t && node_t[nb+s] >= t && node_t[nb+tt] >= t && s != tt)
                  ? 1.f : 0.f;
        me[d] = m; emf[ge] = m;
        if (m > 0.f){ atomicAdd(&dg[s], 1.f); atomicAdd(&dg[tt], 1.f); }
    }
    __syncthreads();
    for (int e = 0; e < EPGc; e++){
        if (me[e] == 0.f) continue;
        int ge = eb + e;
        int s = src[ge] - nb, t = dst[ge] - nb;
        float ds  = rsqrtf(fmaxf(dg[s], 1.f));
        float dt_ = rsqrtf(fmaxf(dg[t], 1.f));
        float xs = x[(size_t)(nb+s)*Dd + d], xt = x[(size_t)(nb+t)*Dd + d];
        float hs = h[(size_t)(nb+s)*Dd + d], ht = h[(size_t)(nb+t)*Dd + d];
        ax[t*Dd + d] += xs*ds;  ax[s*Dd + d] += xt*dt_;
        ah[t*Dd + d] += hs*ds;  ah[s*Dd + d] += ht*dt_;
    }
    __syncthreads();
    for (int i = 0; i < NPGc; i++){
        aggx[(size_t)(nb+i)*Dd + d] = __float2half_rn(ax[i*Dd + d]);
        aggh[(size_t)(nb+i)*Dd + d] = __float2half_rn(ah[i*Dd + d]);
    }
    if (d < NPGc) deg[nb+d] = dg[d];
}

#define AGG1_SMEM ((NPGc*Dd + 64 + 64)*4)
__global__ void k_agg1_grp(const int* __restrict__ src, const int* __restrict__ dst,
                           const float* __restrict__ emf, const float* __restrict__ deg,
                           const float* __restrict__ rh, __half* __restrict__ agg){
    extern __shared__ float sm[];
    float* as = sm;
    float* dg = sm + NPGc*Dd;
    float* me = dg + 64;
    int b = blockIdx.x, d = threadIdx.x;
    for (int i = d; i < NPGc*Dd; i += 128) as[i] = 0.f;
    int nb = b*NPGc, eb = b*EPGc;
    if (d < NPGc) dg[d] = deg[nb+d];
    if (d < EPGc) me[d] = emf[eb+d];
    __syncthreads();
    for (int e = 0; e < EPGc; e++){
        if (me[e] == 0.f) continue;
        int ge = eb + e;
        int s = src[ge] - nb, t = dst[ge] - nb;
        float ds  = rsqrtf(fmaxf(dg[s], 1.f));
        float dt_ = rsqrtf(fmaxf(dg[t], 1.f));
        as[t*Dd + d] += rh[(size_t)(nb+s)*Dd + d]*ds;
        as[s*Dd + d] += rh[(size_t)(nb+t)*Dd + d]*dt_;
    }
    __syncthreads();
    for (int i = 0; i < NPGc; i++)
        agg[(size_t)(nb+i)*Dd + d] = __float2half_rn(as[i*Dd + d]);
}

// ---------------- conversions (emb + all weights in ONE launch) ---------------
__global__ void k_cvtw(const float* emb, __half* emb16,
                       const float* gwih, __half* gwih16,
                       const float* W1, __half* w116,
                       const float* W2, __half* w216,
                       const float* gwhh, __half* gwhh16){
    int i = blockIdx.x*256 + threadIdx.x;
    const float* in; __half* out; int j;
    if (i < 3276800){ in = emb; out = emb16; j = i; }
    else if (i < 3301376){ in = gwih; out = gwih16; j = i - 3276800; }
    else if (i < 3305472){ in = W1; out = w116; j = i - 3301376; }
    else if (i < 3309568){ in = W2; out = w216; j = i - 3305472; }
    else if (i < 3321856){ in = gwhh; out = gwhh16; j = i - 3309568; }
    else return;
    float4 v = ((const float4*)in)[j];
    ((__half2*)out)[2*j]   = __floats2half2_rn(v.x, v.y);
    ((__half2*)out)[2*j+1] = __floats2half2_rn(v.z, v.w);
}

__global__ void k_cvt2(const float* a, __half* ah, int na4,
                       const float* b, __half* bh, int nb4){
    int i = blockIdx.x*256 + threadIdx.x;
    const float* in; __half* out; int j;
    if (i < na4){ in = a; out = ah; j = i; }
    else if (i - na4 < nb4){ in = b; out = bh; j = i - na4; }
    else return;
    float4 v = ((const float4*)in)[j];
    ((__half2*)out)[2*j]   = __floats2half2_rn(v.x, v.y);
    ((__half2*)out)[2*j+1] = __floats2half2_rn(v.z, v.w);
}

// ---------------- helpers -----------------------------------------------------
__global__ void k_gather_norm(const float* __restrict__ emb, const int* __restrict__ iid,
                              float* __restrict__ out, __half* __restrict__ out16){
    int n = blockIdx.x, d = threadIdx.x;
    float v = emb[(size_t)iid[n]*Dd + d];
    float s = v*v;
    #pragma unroll
    for (int o = 16; o; o >>= 1) s += __shfl_xor_sync(0xffffffffu, s, o);
    __shared__ float sh[4];
    if ((d & 31) == 0) sh[d>>5] = s;
    __syncthreads();
    float tot = sh[0]+sh[1]+sh[2]+sh[3];
    float nf = v / fmaxf(sqrtf(tot), 1e-12f);
    out[(size_t)n*Dd + d] = nf;
    out16[(size_t)n*Dd + d] = __float2half_rn(nf);
}

__global__ void k_row_norm_h(const float* __restrict__ in, float* __restrict__ out,
                             __half* __restrict__ out16){
    int n = blockIdx.x, d = threadIdx.x;
    float v = in[(size_t)n*Dd + d];
    float s = v*v;
    #pragma unroll
    for (int o = 16; o; o >>= 1) s += __shfl_xor_sync(0xffffffffu, s, o);
    __shared__ float sh[4];
    if ((d & 31) == 0) sh[d>>5] = s;
    __syncthreads();
    float tot = sh[0]+sh[1]+sh[2]+sh[3];
    float nf = v / fmaxf(sqrtf(tot), 1e-12f);
    out[(size_t)n*Dd + d] = nf;
    if (out16) out16[(size_t)n*Dd + d] = __float2half_rn(nf);
}

__global__ void k_emb_scale(const float* __restrict__ emb, float* __restrict__ sc){
    int v = blockIdx.x, d = threadIdx.x;
    float x = emb[(size_t)v*Dd + d];
    float s = x*x;
    #pragma unroll
    for (int o = 16; o; o >>= 1) s += __shfl_xor_sync(0xffffffffu, s, o);
    __shared__ float sh[4];
    if ((d & 31) == 0) sh[d>>5] = s;
    __syncthreads();
    if (d == 0){
        float tot = sh[0]+sh[1]+sh[2]+sh[3];
        sc[v] = NSCALE / fmaxf(sqrtf(tot), 1e-12f);
    }
}

// pack transposed weights + biases + zero expsum/tend (all fused)
__global__ void k_pack(const float* Wxr, const float* Wxz, const float* Wxh,
                       const float* Whr, const float* Whz, const float* Whh,
                       const float* Wu, const float* Wv, const float* W_sr,
                       const float* bxr, const float* bxz, const float* bxh,
                       const float* bhr, const float* bhz,
                       __half* WcxT, __half* WchT, __half* WhhT,
                       __half* WuT, __half* WvT, __half* WsrT,
                       float* bcx, float* bch,
                       float* expsum, float* tend){
    int i = blockIdx.x*256 + threadIdx.x;
    if (i < 49152){
        int j = i >> 7, k = i & 127;
        const float* W = (j < 128) ? Wxr : ((j < 256) ? Wxz : Wxh);
        WcxT[i] = __float2half_rn(W[k*128 + (j & 127)]);
    } else if (i < 81920){
        int t = i - 49152;
        int j = t >> 7, k = t & 127;
        const float* W = (j < 128) ? Whr : Whz;
        WchT[t] = __float2half_rn(W[k*128 + (j & 127)]);
    } else if (i < 98304){
        int t = i - 81920;
        int j = t >> 7, k = t & 127;
        WhhT[t] = __float2half_rn(Whh[k*128 + j]);
    } else if (i < 114688){
        int t = i - 98304;
        int j = t >> 7, k = t & 127;
        WuT[t] = __float2half_rn(Wu[k*128 + j]);
    } else if (i < 131072){
        int t = i - 114688;
        int j = t >> 7, k = t & 127;
        WvT[t] = __float2half_rn(Wv[k*128 + j]);
    } else if (i < 163840){
        int t = i - 131072;
        int j = t >> 8, k = t & 255;
        WsrT[t] = __float2half_rn(W_sr[k*128 + j]);
    } else if (i < 164224){
        int j = i - 163840;
        bcx[j] = (j < 128) ? bxr[j] : ((j < 256) ? bxz[j-128] : bxh[j-256]);
    } else if (i < 164480){
        int j = i - 164224;
        bch[j] = (j < 128) ? bhr[j] : bhz[j-128];
    } else if (i < 164480 + Bq){
        expsum[i - 164480] = 0.f;
    } else if (i == 164480 + Bq){
        tend[0] = 0.f;
    }
}

// ---------------- fused GRU + l2norm + copy to x,h ----------------------------
__global__ void k_gru_norm(const float* __restrict__ gi, const float* __restrict__ gh,
                           float* __restrict__ feat, float* __restrict__ x,
                           float* __restrict__ h){
    int n = blockIdx.x, d = threadIdx.x;
    size_t b3 = (size_t)n*384 + d;
    float ir = gi[b3], iz = gi[b3+128], ig = gi[b3+256];
    float hr = gh[b3], hz = gh[b3+128], hg = gh[b3+256];
    float r = 1.f/(1.f + expf(-(ir + hr)));
    float z = 1.f/(1.f + expf(-(iz + hz)));
    float g = tanhf(ig + r*hg);
    size_t i = (size_t)n*Dd + d;
    float f = (1.f - z)*g + z*feat[i];
    float s = f*f;
    #pragma unroll
    for (int o = 16; o; o >>= 1) s += __shfl_xor_sync(0xffffffffu, s, o);
    __shared__ float sh[4];
    if ((d & 31) == 0) sh[d>>5] = s;
    __syncthreads();
    float tot = sh[0]+sh[1]+sh[2]+sh[3];
    float nf = f / fmaxf(sqrtf(tot), 1e-12f);
    feat[i] = nf; x[i] = nf; h[i] = nf;
}

__global__ void k_tmax(const float* __restrict__ et, float* tend){
    int i = blockIdx.x*256 + threadIdx.x;
    float v = (i < EE) ? et[i] : 0.f;
    #pragma unroll
    for (int o = 16; o; o >>= 1) v = fmaxf(v, __shfl_xor_sync(0xffffffffu, v, o));
    if ((threadIdx.x & 31) == 0) atomicMax((int*)tend, __float_as_int(v));
}

__global__ void k_rz(const float* __restrict__ Gx, const float* __restrict__ Gh,
                     const float* __restrict__ h, float* __restrict__ zz,
                     float* __restrict__ rh){
    int i = blockIdx.x*256 + threadIdx.x;
    if (i >= ND) return;
    int n = i >> 7, d = i & 127;
    size_t bx = (size_t)n*384 + d, bh = (size_t)n*256 + d;
    float rr = 1.f/(1.f + expf(-(Gx[bx]     + Gh[bh]    )));
    float zv = 1.f/(1.f + expf(-(Gx[bx+128] + Gh[bh+128])));
    zz[i] = zv;
    rh[i] = rr * h[i];
}

__global__ void k_upd(const float* __restrict__ Gx, const float* __restrict__ t2,
                      const float* __restrict__ zz, const float* __restrict__ node_t,
                      const float* __restrict__ tend, int kstep, float* __restrict__ h){
    int i = blockIdx.x*256 + threadIdx.x;
    if (i >= ND) return;
    int n = i >> 7, d = i & 127;
    float uu = tanhf(Gx[(size_t)n*384 + 256 + d] + t2[i]);
    float dt = tend[0] / (float)NSPLITS;
    float t = (float)kstep * dt;
    float hv = h[i];
    float dh = (node_t[n] >= t) ? (1.f - zz[i])*(uu - hv) : 0.f;
    h[i] = hv + dt*dh;
}

// ---------------- attention readout (writes f32 + fp16 cc) --------------------
__global__ void k_attn(const float* __restrict__ feat, const float* __restrict__ q,
                       const float* __restrict__ fwu, const float* __restrict__ We,
                       float* __restrict__ cc, __half* __restrict__ cc16){
    int b = blockIdx.x, d = threadIdx.x;
    __shared__ float e_sh[NPGc];
    __shared__ float red[4];
    const float* fb  = feat + (size_t)b*NPGc*Dd;
    const float* fwb = fwu  + (size_t)b*NPGc*Dd;
    float qd = q[(size_t)b*Dd + d];
    float wed = We[d];
    for (int i = 0; i < NPGc; i++){
        float s = (1.f/(1.f + expf(-(fwb[(size_t)i*Dd + d] + qd)))) * wed;
        #pragma unroll
        for (int o = 16; o; o >>= 1) s += __shfl_xor_sync(0xffffffffu, s, o);
        if ((d & 31) == 0) red[d>>5] = s;
        __syncthreads();
        if (d == 0) e_sh[i] = red[0]+red[1]+red[2]+red[3];
        __syncthreads();
    }
    float mx = -1e30f;
    for (int i = 0; i < NPGc; i++) mx = fmaxf(mx, e_sh[i]);
    float sm = 0.f;
    for (int i = 0; i < NPGc; i++) sm += expf(e_sh[i] - mx);
    float srg = 0.f;
    for (int i = 0; i < NPGc; i++) srg += fb[(size_t)i*Dd + d]*(expf(e_sh[i] - mx)/sm);
    float last = fb[(size_t)(NPGc-1)*Dd + d];
    cc[(size_t)b*2*Dd + d]      = last;
    cc[(size_t)b*2*Dd + Dd + d] = srg;
    cc16[(size_t)b*2*Dd + d]      = __float2half_rn(last);
    cc16[(size_t)b*2*Dd + Dd + d] = __float2half_rn(srg);
}

// float4-vectorized subtract (Vv divisible by 4)
__global__ void k_sub(float* __restrict__ out, const float* __restrict__ expsum){
    int v4 = blockIdx.x*256 + threadIdx.x;
    int b = blockIdx.y;
    if (v4 >= Vv/4) return;
    float l = 12.f + logf(expsum[b]);
    float4* p = (float4*)(out + (size_t)b*Vv) + v4;
    float4 x = *p;
    x.x -= l; x.y -= l; x.z -= l; x.w -= l;
    *p = x;
}

// ---------------- host orchestration ------------------------------------------
static inline void gemm16(const __half* A, int lda, const __half* B, int ldb,
                          const float* bias, const float* cs,
                          const float* rs, int rsMode,
                          float* C, int ldc, float* expsum,
                          int Nr, int Mc, int K, int accum = 0){
    dim3 grid((Nr + 127)/128, (Mc + 127)/128);
    k_gemm_h<<<grid, 256>>>(A, lda, B, ldb, bias, cs, rs, rsMode,
                            C, ldc, expsum, Nr, Mc, K, accum);
}

extern "C" void kernel_launch(void* const* d_in, const int* in_sizes, int n_in,
                              void* d_out, int out_size)
{
    const int*   iid    = (const int*)  d_in[0];
    const int*   src    = (const int*)  d_in[1];
    const int*   dst    = (const int*)  d_in[2];
    const float* edge_w = (const float*)d_in[3];
    const float* edge_t = (const float*)d_in[4];
    const float* node_t = (const float*)d_in[5];
    const float* emb    = (const float*)d_in[6];
    const float* W1     = (const float*)d_in[7];
    const float* W2     = (const float*)d_in[8];
    const float* gw_ih  = (const float*)d_in[9];
    const float* gw_hh  = (const float*)d_in[10];
    const float* gb_ih  = (const float*)d_in[11];
    const float* gb_hh  = (const float*)d_in[12];
    const float* Wxr = (const float*)d_in[13]; const float* bxr = (const float*)d_in[14];
    const float* Wxz = (const float*)d_in[15]; const float* bxz = (const float*)d_in[16];
    const float* Wxh = (const float*)d_in[17]; const float* bxh = (const float*)d_in[18];
    const float* Whr = (const float*)d_in[19]; const float* bhr = (const float*)d_in[20];
    const float* Whz = (const float*)d_in[21]; const float* bhz = (const float*)d_in[22];
    const float* Whh = (const float*)d_in[23]; const float* bhh = (const float*)d_in[24];
    const float* Wu  = (const float*)d_in[25];
    const float* Wv  = (const float*)d_in[26];
    const float* bv  = (const float*)d_in[27];
    const float* We  = (const float*)d_in[28];
    const float* W_sr= (const float*)d_in[29];
    float* out = (float*)d_out;

    static int s_attr_done = 0;
    if (!s_attr_done){
        cudaFuncSetAttribute(k_edgeB_grp, cudaFuncAttributeMaxDynamicSharedMemorySize, EDGEB_SMEM);
        cudaFuncSetAttribute(k_agg2_grp,  cudaFuncAttributeMaxDynamicSharedMemorySize, AGG2_SMEM);
        cudaFuncSetAttribute(k_agg1_grp,  cudaFuncAttributeMaxDynamicSharedMemorySize, AGG1_SMEM);
        s_attr_done = 1;
    }

    float *p_feat,*p_nv,*p_gi,*p_gh,*p_x,*p_h,*p_t1,*p_t2,*p_rh,*p_zz;
    float *p_emf,*p_tend,*p_sc,*p_q,*p_cc,*p_sr,*p_bcx,*p_bch,*p_expsum;
    __half *p_agg16,*p_feat16,*p_cc16,*p_sr16,*p_emb16,*p_gwih16,*p_w116,*p_w216;
    __half *p_gwhh16,*p_wcxT16,*p_wchT16,*p_whhT16,*p_wuT16,*p_wvT16,*p_wsrT16;
    __half *p_wc1T16,*p_wc2T16;
    cudaGetSymbolAddress((void**)&p_feat, g_feat);
    cudaGetSymbolAddress((void**)&p_nv,   g_nv);
    cudaGetSymbolAddress((void**)&p_gi,   g_gi);
    cudaGetSymbolAddress((void**)&p_gh,   g_gh);
    cudaGetSymbolAddress((void**)&p_x,    g_x);
    cudaGetSymbolAddress((void**)&p_h,    g_h);
    cudaGetSymbolAddress((void**)&p_t1,   g_t1);
    cudaGetSymbolAddress((void**)&p_t2,   g_t2);
    cudaGetSymbolAddress((void**)&p_rh,   g_rh);
    cudaGetSymbolAddress((void**)&p_zz,   g_zz);
    cudaGetSymbolAddress((void**)&p_emf,  g_emf);
    cudaGetSymbolAddress((void**)&p_tend, g_tend);
    cudaGetSymbolAddress((void**)&p_sc,   g_sc);
    cudaGetSymbolAddress((void**)&p_q,    g_q);
    cudaGetSymbolAddress((void**)&p_cc,   g_cc);
    cudaGetSymbolAddress((void**)&p_sr,   g_sr);
    cudaGetSymbolAddress((void**)&p_bcx,  g_bcx);
    cudaGetSymbolAddress((void**)&p_bch,  g_bch);
    cudaGetSymbolAddress((void**)&p_expsum, g_expsum);
    cudaGetSymbolAddress((void**)&p_agg16, g_agg16);
    cudaGetSymbolAddress((void**)&p_feat16,g_feat16);
    cudaGetSymbolAddress((void**)&p_cc16, g_cc16);
    cudaGetSymbolAddress((void**)&p_sr16, g_sr16);
    cudaGetSymbolAddress((void**)&p_emb16,g_emb16);
    cudaGetSymbolAddress((void**)&p_gwih16,g_gwih16);
    cudaGetSymbolAddress((void**)&p_w116, g_w116);
    cudaGetSymbolAddress((void**)&p_w216, g_w216);
    cudaGetSymbolAddress((void**)&p_gwhh16,g_gwhh16);
    cudaGetSymbolAddress((void**)&p_wcxT16,g_wcxT16);
    cudaGetSymbolAddress((void**)&p_wchT16,g_wchT16);
    cudaGetSymbolAddress((void**)&p_whhT16,g_whhT16);
    cudaGetSymbolAddress((void**)&p_wuT16, g_wuT16);
    cudaGetSymbolAddress((void**)&p_wvT16, g_wvT16);
    cudaGetSymbolAddress((void**)&p_wsrT16,g_wsrT16);
    cudaGetSymbolAddress((void**)&p_wc1T16,g_wc1T16);
    cudaGetSymbolAddress((void**)&p_wc2T16,g_wc2T16);

    __half* p_aggx16 = p_agg16;
    __half* p_aggh16 = p_agg16 + ND;
    __half* p_aggrh16= p_agg16 + 2*ND;
    float* p_den1  = p_nv;
    float* p_den2  = p_nv + NN;
    float* p_deg   = p_nv + 2*NN;

    // ---- Stage A + weight prep ----
    k_gather_norm<<<NN, 128>>>(emb, iid, p_feat, p_feat16);
    k_emb_scale<<<Vv, 128>>>(emb, p_sc);
    k_cvtw<<<(3321856 + 255)/256, 256>>>(emb, p_emb16, gw_ih, p_gwih16,
                                         W1, p_w116, W2, p_w216, gw_hh, p_gwhh16);
    k_pack<<<(164480 + Bq + 1 + 255)/256, 256>>>(Wxr, Wxz, Wxh, Whr, Whz, Whh, Wu, Wv, W_sr,
                                      bxr, bxz, bxh, bhr, bhz,
                                      p_wcxT16, p_wchT16, p_whhT16, p_wuT16, p_wvT16,
                                      p_wsrT16, p_bcx, p_bch, p_expsum, p_tend);
    gemm16(p_gwih16,       256, p_w116, 128, nullptr, nullptr, nullptr, 0,
           p_t1, 128, nullptr, 384, 128, 128);
    gemm16(p_gwih16 + 128, 256, p_w216, 128, nullptr, nullptr, nullptr, 0,
           p_t2, 128, nullptr, 384, 128, 128);
    k_cvt2<<<(2*12288 + 255)/256, 256>>>(p_t1, p_wc1T16, 12288, p_t2, p_wc2T16, 12288);

    // ---- Stage B ----
    k_edgeB_grp<<<Bq, 128, EDGEB_SMEM>>>(src, dst, edge_w, p_feat,
                                         p_aggx16, p_aggh16, p_den1, p_den2);
    k_tmax<<<(EE+255)/256, 256>>>(edge_t, p_tend);

    // ---- Stage C ----
    gemm16(p_aggx16, Dd, p_wc1T16, 128, gb_ih,  nullptr, p_den1, 1,
           p_gi, 384, nullptr, NN, 384, Dd, 0);
    gemm16(p_aggh16, Dd, p_wc2T16, 128, nullptr, nullptr, p_den2, 1,
           p_gi, 384, nullptr, NN, 384, Dd, 1);
    gemm16(p_feat16, Dd, p_gwhh16, 128, gb_hh, nullptr, nullptr, 0,
           p_gh, 384, nullptr, NN, 384, Dd, 0);

    // ---- Stage D ----
    k_gru_norm<<<NN, 128>>>(p_gi, p_gh, p_feat, p_x, p_h);

    // ---- Stage E: ODE (R12 structure: 7 launches/step) ----
    for (int k = 0; k < NSPLITS; k++){
        k_agg2_grp<<<Bq, 128, AGG2_SMEM>>>(src, dst, edge_t, node_t, p_tend, k,
                                           p_x, p_h, p_aggx16, p_aggh16, p_emf, p_deg);
        gemm16(p_aggx16, Dd, p_wcxT16, 128, p_bcx, nullptr, p_deg, 2,
               p_gi, 384, nullptr, NN, 384, Dd, 0);
        gemm16(p_aggh16, Dd, p_wchT16, 128, p_bch, nullptr, p_deg, 2,
               p_gh, 256, nullptr, NN, 256, Dd, 0);
        k_rz<<<(ND+255)/256, 256>>>(p_gi, p_gh, p_h, p_zz, p_rh);
        k_agg1_grp<<<Bq, 128, AGG1_SMEM>>>(src, dst, p_emf, p_deg, p_rh, p_aggrh16);
        gemm16(p_aggrh16, Dd, p_whhT16, 128, bhh, nullptr, p_deg, 2,
               p_t2, Dd, nullptr, NN, Dd, Dd, 0);
        k_upd<<<(ND+255)/256, 256>>>(p_gi, p_t2, p_zz, node_t, p_tend, k, p_h);
    }
    k_row_norm_h<<<NN, 128>>>(p_h, p_feat, p_feat16);

    // ---- Stage F ----
    gemm16(p_feat16, Dd, p_wuT16, 128, nullptr, nullptr, nullptr, 0,
           p_t1, Dd, nullptr, NN, Dd, Dd, 0);
    gemm16(p_feat16 + (size_t)(NPGc-1)*Dd, NPGc*Dd, p_wvT16, 128, bv, nullptr, nullptr, 0,
           p_q, Dd, nullptr, Bq, Dd, Dd, 0);
    k_attn<<<Bq, 128>>>(p_feat, p_q, p_t1, We, p_cc, p_cc16);
    gemm16(p_cc16, 2*Dd, p_wsrT16, 256, nullptr, nullptr, nullptr, 0,
           p_sr, Dd, nullptr, Bq, Dd, 2*Dd, 0);
    k_row_norm_h<<<Bq, 128>>>(p_sr, p_sr, p_sr16);

    // ---- Stage G ----
    gemm16(p_sr16, Dd, p_emb16, 128, nullptr, p_sc, nullptr, 0,
           out, Vv, p_expsum, Bq, Vv, Dd, 0);
    k_sub<<<dim3((Vv/4+255)/256, Bq), 256>>>(out, p_expsum);
}